// round 10
// baseline (speedup 1.0000x reference)
#include <cuda_runtime.h>
#include <math.h>

#define Bb   1024
#define Ll   256
#define Mm   256
#define Hh   64
#define Vv   64
#define NB   8      // batches per block
#define NBLK 128
#define NT   256

// ---------------- device scratch ----------------
__device__ float d_E2[Vv * 192];       // embed @ Wx^T + b_ih   (64 x 192)
__device__ float d_A2[Hh * Hh];        // (q_w^T k_w) / 8  stored [a][l]
__device__ float d_a0[Hh];             // (q_b^T k_w) / 8
__device__ float d_gpart[Ll * NBLK];   // per-step per-block partial sums (+1.0 sentinel)

__device__ __forceinline__ float sigf(float x)     { return 1.f / (1.f + __expf(-x)); }
__device__ __forceinline__ float tanhfast(float x) { return 2.f / (1.f + __expf(-2.f * x)) - 1.f; }

__device__ __forceinline__ unsigned long long pack2(float a, float b) {
    unsigned long long r;
    asm("mov.b64 %0, {%1, %2};" : "=l"(r) : "f"(a), "f"(b));
    return r;
}
__device__ __forceinline__ void unpack2(unsigned long long v, float& a, float& b) {
    asm("mov.b64 {%0, %1}, %2;" : "=f"(a), "=f"(b) : "l"(v));
}
__device__ __forceinline__ void fma2(unsigned long long& d, unsigned long long a, unsigned long long b) {
    asm("fma.rn.f32x2 %0, %1, %2, %0;" : "+l"(d) : "l"(a), "l"(b));
}

// ---------------- prep ----------------
__global__ void prep_kernel(const float* __restrict__ embed,
                            const float* __restrict__ gwih,
                            const float* __restrict__ gbih,
                            const float* __restrict__ kw,
                            const float* __restrict__ qw,
                            const float* __restrict__ qb) {
    const int idx = blockIdx.x * blockDim.x + threadIdx.x;
    const int stride = gridDim.x * blockDim.x;
    for (int i = idx; i < Vv * 192; i += stride) {
        const int v = i / 192, k = i % 192;
        float s = gbih[k];
        const float* e = embed + v * Hh;
        const float* w = gwih + k * (2 * Hh);
        #pragma unroll 8
        for (int j = 0; j < Hh; j++) s = fmaf(e[j], w[j], s);
        d_E2[i] = s;
    }
    for (int i = idx; i < Hh * Hh; i += stride) {
        const int a = i >> 6, l = i & 63;
        float s = 0.f;
        for (int t = 0; t < Hh; t++) s = fmaf(kw[t * Hh + a], qw[t * Hh + l], s);
        d_A2[i] = s * 0.125f;
    }
    for (int i = idx; i < Hh; i += stride) {
        float s = 0.f;
        for (int t = 0; t < Hh; t++) s = fmaf(kw[t * Hh + i], qb[t], s);
        d_a0[i] = s * 0.125f;
    }
    for (int i = idx; i < Ll * NBLK; i += stride) d_gpart[i] = 0.f;
}

// ---------------- SMEM layout (float offsets) ----------------
#define OFF_GWHH 0        /* gwhh [k<192][j<64] pad 68 = 13056 (row-major, j-contig) */
#define OFF_E2   13056    /* full E2 table [v<64][k<192] = 12288 */
#define OFF_LWIH 25344    /* lwih [k<128][j<64] pad 68 = 8704 (row-major, j-contig) */
#define OFF_LWHH 34048    /* [j<32][u<32][g<4] = 4096 */
#define OFF_A2   38144    /* A2^T [l][a] = 4096 */
#define OFF_VW   42240    /* vw^T [j][k] = 4096 */
#define OFF_GBHH 46336    /* 192 */
#define OFF_LB2  46528    /* 128 lbih+lbhh */
#define OFF_A0   46656    /* 64 */
#define OFF_VB   46720    /* 64 */
#define OFF_TW   46784    /* 32 */
#define OFF_SC   46816    /* 4 */
#define OFF_HP   46820    /* 8x64 h state (16B-aligned) */
#define OFF_XW   47332    /* ring 4 x 8 x 128 (bias folded) */
#define OFF_GH   51428    /* 8 x 192 */
#define OFF_GI   52964    /* 8 x 192 */
#define OFF_Q2   54500    /* 8x64 */
#define OFF_WS   55012    /* 8x64 */
#define OFF_RET  55524    /* 8x64 */
#define OFF_PROB 56036    /* 8 */
#define OFF_RED  56044    /* 128 */
#define OFF_TOK  56172    /* 2 x 8 ints */
#define SMEM_FLOATS 56188
#define SMEM_BYTES  (SMEM_FLOATS * 4)

__global__ void __launch_bounds__(NT, 1) model_kernel(
    const int*   __restrict__ seq,
    const float* __restrict__ memory,
    const float* __restrict__ gwih,
    const float* __restrict__ gwhh,
    const float* __restrict__ gbhh,
    const float* __restrict__ vw,
    const float* __restrict__ vb,
    const float* __restrict__ lwih,
    const float* __restrict__ lwhh,
    const float* __restrict__ lbih,
    const float* __restrict__ lbhh,
    const float* __restrict__ trigw,
    const float* __restrict__ trigb,
    const float* __restrict__ headw,
    const float* __restrict__ headb,
    float* __restrict__ out,
    int out_size)
{
    extern __shared__ float sm[];
    const int tid = threadIdx.x;
    const int b0  = blockIdx.x * NB;
    int* s_tok = (int*)(sm + OFF_TOK);

    // ---- weight staging ----
    for (int i = tid; i < 192 * 64; i += NT) {           // gwhh row-major, pad 68
        const int k = i >> 6, j = i & 63;
        sm[OFF_GWHH + k * 68 + j] = gwhh[i];
    }
    for (int i = tid; i < 12288; i += NT)                // full E2 table
        sm[OFF_E2 + i] = d_E2[i];
    for (int i = tid; i < 128 * 64; i += NT) {           // lwih row-major, pad 68
        const int k = i >> 6, j = i & 63;
        sm[OFF_LWIH + k * 68 + j] = lwih[i];
    }
    for (int i = tid; i < 4096; i += NT) {               // lwhh [j][u][g]
        const int j = i >> 7, u = (i >> 2) & 31, g = i & 3;
        sm[OFF_LWHH + i] = lwhh[(g * 32 + u) * 32 + j];
    }
    for (int i = tid; i < 4096; i += NT)                 // A2^T [l][a]
        sm[OFF_A2 + i] = d_A2[(i % 64) * 64 + (i / 64)];
    for (int i = tid; i < 4096; i += NT)                 // vw^T [j][k]
        sm[OFF_VW + i] = vw[(i % 64) * 64 + (i / 64)];
    for (int i = tid; i < 192; i += NT) sm[OFF_GBHH + i] = gbhh[i];
    for (int i = tid; i < 128; i += NT) sm[OFF_LB2 + i] = lbih[i] + lbhh[i];
    for (int i = tid; i < 64; i += NT)  { sm[OFF_A0 + i] = d_a0[i]; sm[OFF_VB + i] = vb[i]; }
    for (int i = tid; i < 32; i += NT)  sm[OFF_TW + i] = trigw[i];
    if (tid == 0) sm[OFF_SC] = trigb[0];
    for (int i = tid; i < NB * Hh; i += NT) sm[OFF_HP + i] = 0.f;
    for (int i = tid; i < 1536; i += NT) sm[OFF_GH + i] = gbhh[i % 192];   // gh for t=0 (h=0)
    if (tid < NB) s_tok[tid] = seq[(b0 + tid) * Ll + 0];                    // tokens t=0 -> slot 0
    __syncthreads();

    int read_prev = 0;
    int nreads = 0;

    // lane->LSTM mapping (warps 4-7): 2 batches per warp, 16 lanes per batch,
    // each lane owns units u0 and u0+16 of its batch.
    const int l_w    = tid >> 5;
    const int l_lane = tid & 31;
    const int l_half = l_lane >> 4;                 // 0/1 within warp
    const int l_bb   = (l_w - 4) * 2 + l_half;      // batch for warps 4-7
    const int l_u0   = l_lane & 15;                 // unit pair (u0, u0+16)

    for (int t = 0; t < Ll; t++) {
        // ===== B: GRU combine -> new h =====
        #pragma unroll
        for (int it = tid; it < NB * Hh; it += NT) {
            const int b = it >> 6, k = it & 63;
            const int tok = s_tok[(t & 1) * 8 + b];
            float gi_r = sm[OFF_E2 + tok * 192 + k];
            float gi_z = sm[OFF_E2 + tok * 192 + 64 + k];
            float gi_n = sm[OFF_E2 + tok * 192 + 128 + k];
            if (read_prev) {
                gi_r += sm[OFF_GI + b * 192 + k];
                gi_z += sm[OFF_GI + b * 192 + 64 + k];
                gi_n += sm[OFF_GI + b * 192 + 128 + k];
            }
            const float gh_r = sm[OFF_GH + b * 192 + k];
            const float gh_z = sm[OFF_GH + b * 192 + 64 + k];
            const float gh_n = sm[OFF_GH + b * 192 + 128 + k];
            const float r = sigf(gi_r + gh_r);
            const float z = sigf(gi_z + gh_z);
            const float n = tanhfast(fmaf(r, gh_n, gi_n));
            const float h = sm[OFF_HP + b * 64 + k];
            sm[OFF_HP + b * 64 + k] = n + z * (h - n);   // (1-z)n + z h
        }
        __syncthreads();   // s1

        // LSTM carry registers (warps 4-7), persist X -> Y
        float hh0 = 0.f, hh1 = 0.f, cc0 = 0.f, cc1 = 0.f;

        // ===== X: xW_t (warps 0-3, f32x2 8-batch tiles) || LSTM substeps 0-2 (warps 4-7) =====
        if (tid < 128) {
            const int k = tid;
            const ulonglong2* wrow = (const ulonglong2*)&sm[OFF_LWIH + k * 68];
            unsigned long long acc[NB];
            {
                const unsigned long long binit = pack2(sm[OFF_LB2 + k], 0.f);
                #pragma unroll
                for (int b = 0; b < NB; b++) acc[b] = binit;
            }
            #pragma unroll 4
            for (int g = 0; g < 16; g++) {
                const ulonglong2 w2 = wrow[g];
                #pragma unroll
                for (int b = 0; b < NB; b++) {
                    const ulonglong2 h2 = *(const ulonglong2*)&sm[OFF_HP + b * 64 + g * 4];
                    fma2(acc[b], w2.x, h2.x);
                    fma2(acc[b], w2.y, h2.y);
                }
            }
            float* xw = &sm[OFF_XW + (t & 3) * 1024];
            #pragma unroll
            for (int b = 0; b < NB; b++) {
                float lo, hi;
                unpack2(acc[b], lo, hi);
                xw[b * 128 + k] = lo + hi;
            }
        } else if (t >= 3) {
            // LSTM substeps 0-2 for batch l_bb, units (l_u0, l_u0+16)
            #pragma unroll
            for (int s = 0; s < 3; s++) {
                const int slot = (t + 1 + s) & 3;
                const float* xw = &sm[OFF_XW + slot * 1024 + l_bb * 128];
                float gI0 = xw[l_u0],      gF0 = xw[32 + l_u0],
                      gG0 = xw[64 + l_u0], gO0 = xw[96 + l_u0];
                float gI1 = xw[16 + l_u0],      gF1 = xw[48 + l_u0],
                      gG1 = xw[80 + l_u0],      gO1 = xw[112 + l_u0];
                if (s > 0) {
                    #pragma unroll
                    for (int j = 0; j < 32; j++) {
                        const float hj = __shfl_sync(0xffffffffu,
                                                     (j < 16) ? hh0 : hh1,
                                                     (l_half << 4) + (j & 15));
                        const float4 w0 = *(const float4*)&sm[OFF_LWHH + (j * 32 + l_u0) * 4];
                        const float4 w1 = *(const float4*)&sm[OFF_LWHH + (j * 32 + l_u0 + 16) * 4];
                        gI0 = fmaf(w0.x, hj, gI0); gF0 = fmaf(w0.y, hj, gF0);
                        gG0 = fmaf(w0.z, hj, gG0); gO0 = fmaf(w0.w, hj, gO0);
                        gI1 = fmaf(w1.x, hj, gI1); gF1 = fmaf(w1.y, hj, gF1);
                        gG1 = fmaf(w1.z, hj, gG1); gO1 = fmaf(w1.w, hj, gO1);
                    }
                }
                float c0 = sigf(gI0) * tanhfast(gG0);
                float c1 = sigf(gI1) * tanhfast(gG1);
                if (s > 0) {
                    c0 = fmaf(sigf(gF0), cc0, c0);
                    c1 = fmaf(sigf(gF1), cc1, c1);
                }
                cc0 = c0; hh0 = sigf(gO0) * tanhfast(c0);
                cc1 = c1; hh1 = sigf(gO1) * tanhfast(c1);
            }
        }
        __syncthreads();   // s2

        // ===== Y: gh_{t+1} k<128 (warps 0-3) || LSTM substep 3 + prob (warps 4-7) =====
        if (tid < 128) {
            const int k = tid;
            const ulonglong2* wrow = (const ulonglong2*)&sm[OFF_GWHH + k * 68];
            unsigned long long acc[NB];
            {
                const unsigned long long binit = pack2(sm[OFF_GBHH + k], 0.f);
                #pragma unroll
                for (int b = 0; b < NB; b++) acc[b] = binit;
            }
            #pragma unroll 4
            for (int g = 0; g < 16; g++) {
                const ulonglong2 w2 = wrow[g];
                #pragma unroll
                for (int b = 0; b < NB; b++) {
                    const ulonglong2 h2 = *(const ulonglong2*)&sm[OFF_HP + b * 64 + g * 4];
                    fma2(acc[b], w2.x, h2.x);
                    fma2(acc[b], w2.y, h2.y);
                }
            }
            #pragma unroll
            for (int b = 0; b < NB; b++) {
                float lo, hi;
                unpack2(acc[b], lo, hi);
                sm[OFF_GH + b * 192 + k] = lo + hi;
            }
        } else if (t >= 3) {
            const int slot = t & 3;
            const float* xw = &sm[OFF_XW + slot * 1024 + l_bb * 128];
            float gI0 = xw[l_u0],      gF0 = xw[32 + l_u0],
                  gG0 = xw[64 + l_u0], gO0 = xw[96 + l_u0];
            float gI1 = xw[16 + l_u0],      gF1 = xw[48 + l_u0],
                  gG1 = xw[80 + l_u0],      gO1 = xw[112 + l_u0];
            #pragma unroll
            for (int j = 0; j < 32; j++) {
                const float hj = __shfl_sync(0xffffffffu,
                                             (j < 16) ? hh0 : hh1,
                                             (l_half << 4) + (j & 15));
                const float4 w0 = *(const float4*)&sm[OFF_LWHH + (j * 32 + l_u0) * 4];
                const float4 w1 = *(const float4*)&sm[OFF_LWHH + (j * 32 + l_u0 + 16) * 4];
                gI0 = fmaf(w0.x, hj, gI0); gF0 = fmaf(w0.y, hj, gF0);
                gG0 = fmaf(w0.z, hj, gG0); gO0 = fmaf(w0.w, hj, gO0);
                gI1 = fmaf(w1.x, hj, gI1); gF1 = fmaf(w1.y, hj, gF1);
                gG1 = fmaf(w1.z, hj, gG1); gO1 = fmaf(w1.w, hj, gO1);
            }
            const float c0 = fmaf(sigf(gF0), cc0, sigf(gI0) * tanhfast(gG0));
            const float c1 = fmaf(sigf(gF1), cc1, sigf(gI1) * tanhfast(gG1));
            const float hf0 = sigf(gO0) * tanhfast(c0);
            const float hf1 = sigf(gO1) * tanhfast(c1);
            float v = hf0 * sm[OFF_TW + l_u0] + hf1 * sm[OFF_TW + l_u0 + 16];
            #pragma unroll
            for (int o = 8; o > 0; o >>= 1) v += __shfl_xor_sync(0xffffffffu, v, o);
            if (l_u0 == 0) sm[OFF_PROB + l_bb] = sigf(v + sm[OFF_SC]);
        }
        __syncthreads();   // s3

        // ===== Z: gh k in [128,192) (threads 0-63) || tokens || post+poll (192-255) =====
        if (tid < 64) {
            const int k = 128 + tid;
            const ulonglong2* wrow = (const ulonglong2*)&sm[OFF_GWHH + k * 68];
            unsigned long long acc[NB];
            {
                const unsigned long long binit = pack2(sm[OFF_GBHH + k], 0.f);
                #pragma unroll
                for (int b = 0; b < NB; b++) acc[b] = binit;
            }
            #pragma unroll 4
            for (int g = 0; g < 16; g++) {
                const ulonglong2 w2 = wrow[g];
                #pragma unroll
                for (int b = 0; b < NB; b++) {
                    const ulonglong2 h2 = *(const ulonglong2*)&sm[OFF_HP + b * 64 + g * 4];
                    fma2(acc[b], w2.x, h2.x);
                    fma2(acc[b], w2.y, h2.y);
                }
            }
            #pragma unroll
            for (int b = 0; b < NB; b++) {
                float lo, hi;
                unpack2(acc[b], lo, hi);
                sm[OFF_GH + b * 192 + k] = lo + hi;
            }
        } else if (tid >= 64 && tid < 72) {
            if (t + 1 < Ll)
                s_tok[((t + 1) & 1) * 8 + (tid - 64)] = seq[(b0 + tid - 64) * Ll + (t + 1)];
        } else if (tid >= 192 && t >= 3) {
            const int i = tid - 192;                      // 64 pollers, 2 slots each
            if (i == 0) {                                 // poster
                float pv = sm[OFF_PROB + 0] + sm[OFF_PROB + 1] + sm[OFF_PROB + 2] + sm[OFF_PROB + 3]
                         + sm[OFF_PROB + 4] + sm[OFF_PROB + 5] + sm[OFF_PROB + 6] + sm[OFF_PROB + 7];
                asm volatile("st.global.cg.f32 [%0], %1;"
                             :: "l"(&d_gpart[t * NBLK + blockIdx.x]), "f"(pv + 1.f)
                             : "memory");
            }
            const float* g0 = &d_gpart[t * NBLK + i];
            const float* g1 = &d_gpart[t * NBLK + 64 + i];
            float v0, v1;
            do {
                asm volatile("ld.global.cg.f32 %0, [%1];" : "=f"(v0) : "l"(g0) : "memory");
            } while (v0 == 0.f);
            do {
                asm volatile("ld.global.cg.f32 %0, [%1];" : "=f"(v1) : "l"(g1) : "memory");
            } while (v1 == 0.f);
            sm[OFF_RED + i]      = v0 - 1.f;
            sm[OFF_RED + 64 + i] = v1 - 1.f;
        }
        __syncthreads();   // s4

        if (t >= 3) {
            // every warp reduces redundantly -> uniform do_read in registers
            const int ln = tid & 31;
            float s = sm[OFF_RED + ln] + sm[OFF_RED + 32 + ln]
                    + sm[OFF_RED + 64 + ln] + sm[OFF_RED + 96 + ln];
            #pragma unroll
            for (int o = 16; o > 0; o >>= 1) s += __shfl_xor_sync(0xffffffffu, s, o);
            const int do_read = (s > 512.f);

            if (do_read) {
                // ---- attention: q2 = A2 h + a0 ----
                if (tid < 64) {
                    const int k = tid;
                    float acc[NB];
                    #pragma unroll
                    for (int b = 0; b < NB; b++) acc[b] = sm[OFF_A0 + k];
                    #pragma unroll 4
                    for (int j = 0; j < 64; j += 4) {
                        const float w0 = sm[OFF_A2 + (j + 0) * 64 + k];
                        const float w1 = sm[OFF_A2 + (j + 1) * 64 + k];
                        const float w2 = sm[OFF_A2 + (j + 2) * 64 + k];
                        const float w3 = sm[OFF_A2 + (j + 3) * 64 + k];
                        #pragma unroll
                        for (int b = 0; b < NB; b++) {
                            const float4 h4 = *(const float4*)&sm[OFF_HP + b * 64 + j];
                            acc[b] = fmaf(w0, h4.x, acc[b]);
                            acc[b] = fmaf(w1, h4.y, acc[b]);
                            acc[b] = fmaf(w2, h4.z, acc[b]);
                            acc[b] = fmaf(w3, h4.w, acc[b]);
                        }
                    }
                    #pragma unroll
                    for (int b = 0; b < NB; b++) sm[OFF_Q2 + b * 64 + k] = acc[b];
                }
                __syncthreads();
                {   // streaming online softmax over memory (warp per batch)
                    const int w2 = tid >> 5, l2 = tid & 31;
                    const float* mb = memory + (size_t)(b0 + w2) * (Mm * Hh);
                    const float q0 = sm[OFF_Q2 + w2 * 64 + 2 * l2];
                    const float q1 = sm[OFF_Q2 + w2 * 64 + 2 * l2 + 1];
                    float mx = -3.0e38f, dn = 0.f, ra = 0.f, rb = 0.f;
                    #pragma unroll 4
                    for (int m = 0; m < Mm; m++) {
                        const float2 mmv = *(const float2*)(mb + m * 64 + 2 * l2);
                        float p = q0 * mmv.x + q1 * mmv.y;
                        #pragma unroll
                        for (int o = 16; o > 0; o >>= 1) p += __shfl_xor_sync(0xffffffffu, p, o);
                        const float nm = fmaxf(mx, p);
                        const float f  = __expf(mx - nm);
                        const float e  = __expf(p - nm);
                        dn = fmaf(dn, f, e);
                        ra = fmaf(ra, f, e * mmv.x);
                        rb = fmaf(rb, f, e * mmv.y);
                        mx = nm;
                    }
                    const float inv = 1.f / dn;
                    sm[OFF_WS + w2 * 64 + 2 * l2]     = ra * inv;
                    sm[OFF_WS + w2 * 64 + 2 * l2 + 1] = rb * inv;
                }
                __syncthreads();
                if (tid < 64) {   // retrieved = v_w ws + v_b
                    const int k = tid;
                    float acc[NB];
                    #pragma unroll
                    for (int b = 0; b < NB; b++) acc[b] = sm[OFF_VB + k];
                    #pragma unroll 4
                    for (int j = 0; j < 64; j += 4) {
                        const float w0 = sm[OFF_VW + (j + 0) * 64 + k];
                        const float w1 = sm[OFF_VW + (j + 1) * 64 + k];
                        const float w2 = sm[OFF_VW + (j + 2) * 64 + k];
                        const float w3 = sm[OFF_VW + (j + 3) * 64 + k];
                        #pragma unroll
                        for (int b = 0; b < NB; b++) {
                            const float4 s4 = *(const float4*)&sm[OFF_WS + b * 64 + j];
                            acc[b] = fmaf(w0, s4.x, acc[b]);
                            acc[b] = fmaf(w1, s4.y, acc[b]);
                            acc[b] = fmaf(w2, s4.z, acc[b]);
                            acc[b] = fmaf(w3, s4.w, acc[b]);
                        }
                    }
                    #pragma unroll
                    for (int b = 0; b < NB; b++) sm[OFF_RET + b * 64 + k] = acc[b];
                }
                __syncthreads();
                // GI = Wr . retrieved  (Wr read from global — rare path)
                if (tid < 192) {
                    const int k = tid;
                    float acc[NB];
                    #pragma unroll
                    for (int b = 0; b < NB; b++) acc[b] = 0.f;
                    const float* wr = &gwih[k * 128 + 64];
                    #pragma unroll 4
                    for (int j = 0; j < 64; j += 4) {
                        const float4 w4 = __ldg((const float4*)(wr + j));
                        #pragma unroll
                        for (int b = 0; b < NB; b++) {
                            const float4 r4 = *(const float4*)&sm[OFF_RET + b * 64 + j];
                            acc[b] = fmaf(w4.x, r4.x, acc[b]);
                            acc[b] = fmaf(w4.y, r4.y, acc[b]);
                            acc[b] = fmaf(w4.z, r4.z, acc[b]);
                            acc[b] = fmaf(w4.w, r4.w, acc[b]);
                        }
                    }
                    #pragma unroll
                    for (int b = 0; b < NB; b++) sm[OFF_GI + b * 192 + k] = acc[b];
                }
                __syncthreads();   // protect GI before next-step B
                nreads++;
            }
            read_prev = do_read;
        } else {
            read_prev = 0;
        }
        // next-step B (writes HP) is safe: all HP readers finished before s4
    }

    __syncthreads();
    // ---------- epilogue: logits = h @ head_w^T + head_b ----------
    if (tid < 64) {
        const int k = tid;
        float acc[NB];
        const float hb = __ldg(&headb[k]);
        #pragma unroll
        for (int b = 0; b < NB; b++) acc[b] = hb;
        #pragma unroll 4
        for (int j = 0; j < 64; j += 4) {
            const float4 w4 = __ldg((const float4*)(headw + k * 64 + j));
            #pragma unroll
            for (int b = 0; b < NB; b++) {
                const float4 h4 = *(const float4*)&sm[OFF_HP + b * 64 + j];
                acc[b] = fmaf(w4.x, h4.x, acc[b]);
                acc[b] = fmaf(w4.y, h4.y, acc[b]);
                acc[b] = fmaf(w4.z, h4.z, acc[b]);
                acc[b] = fmaf(w4.w, h4.w, acc[b]);
            }
        }
        #pragma unroll
        for (int b = 0; b < NB; b++) out[(size_t)(b0 + b) * Vv + k] = acc[b];
    }
    if (blockIdx.x == 0 && tid == 0) {
        const float rr = (float)nreads * (1.f / (float)Ll);
        for (int i = Bb * Vv; i < out_size; i++) out[i] = rr;
    }
}

extern "C" void kernel_launch(void* const* d_in, const int* in_sizes, int n_in,
                              void* d_out, int out_size) {
    const int*   seq    = (const int*)  d_in[0];
    const float* memory = (const float*)d_in[1];
    const float* embed  = (const float*)d_in[2];
    const float* gwih   = (const float*)d_in[3];
    const float* gwhh   = (const float*)d_in[4];
    const float* gbih   = (const float*)d_in[5];
    const float* gbhh   = (const float*)d_in[6];
    const float* qw     = (const float*)d_in[7];
    const float* qb     = (const float*)d_in[8];
    const float* kw     = (const float*)d_in[9];
    /* k_b (d_in[10]) cancels in softmax — unused */
    const float* vw     = (const float*)d_in[11];
    const float* vb     = (const float*)d_in[12];
    const float* lwih   = (const float*)d_in[13];
    const float* lwhh   = (const float*)d_in[14];
    const float* lbih   = (const float*)d_in[15];
    const float* lbhh   = (const float*)d_in[16];
    const float* trigw  = (const float*)d_in[17];
    const float* trigb  = (const float*)d_in[18];
    const float* headw  = (const float*)d_in[19];
    const float* headb  = (const float*)d_in[20];
    float* out = (float*)d_out;

    cudaFuncSetAttribute(model_kernel,
                         cudaFuncAttributeMaxDynamicSharedMemorySize, SMEM_BYTES);

    prep_kernel<<<64, 256>>>(embed, gwih, gbih, kw, qw, qb);
    model_kernel<<<NBLK, NT, SMEM_BYTES>>>(seq, memory, gwih, gwhh, gbhh,
                                           vw, vb, lwih, lwhh, lbih, lbhh,
                                           trigw, trigb, headw, headb,
                                           out, out_size);
}

// round 11
// speedup vs baseline: 1.2123x; 1.2123x over previous
#include <cuda_runtime.h>
#include <math.h>

#define Bb   1024
#define Ll   256
#define Mm   256
#define Hh   64
#define Vv   64
#define NB   8      // batches per block
#define NBLK 128
#define NT   256

// ---------------- device scratch ----------------
__device__ float d_E2[Vv * 192];       // embed @ Wx^T + b_ih   (64 x 192)
__device__ float d_A2[Hh * Hh];        // (q_w^T k_w) / 8  stored [a][l]
__device__ float d_a0[Hh];             // (q_b^T k_w) / 8
__device__ float d_gpart[Ll * NBLK];   // per-step per-block partial sums (+1.0 sentinel)

__device__ __forceinline__ float sigf(float x)     { return 1.f / (1.f + __expf(-x)); }
__device__ __forceinline__ float tanhfast(float x) { return 2.f / (1.f + __expf(-2.f * x)) - 1.f; }

__device__ __forceinline__ unsigned long long pack2(float a, float b) {
    unsigned long long r;
    asm("mov.b64 %0, {%1, %2};" : "=l"(r) : "f"(a), "f"(b));
    return r;
}
__device__ __forceinline__ void unpack2(unsigned long long v, float& a, float& b) {
    asm("mov.b64 {%0, %1}, %2;" : "=f"(a), "=f"(b) : "l"(v));
}
__device__ __forceinline__ void fma2(unsigned long long& d, unsigned long long a, unsigned long long b) {
    asm("fma.rn.f32x2 %0, %1, %2, %0;" : "+l"(d) : "l"(a), "l"(b));
}

// ---------------- prep ----------------
__global__ void prep_kernel(const float* __restrict__ embed,
                            const float* __restrict__ gwih,
                            const float* __restrict__ gbih,
                            const float* __restrict__ kw,
                            const float* __restrict__ qw,
                            const float* __restrict__ qb) {
    const int idx = blockIdx.x * blockDim.x + threadIdx.x;
    const int stride = gridDim.x * blockDim.x;
    for (int i = idx; i < Vv * 192; i += stride) {
        const int v = i / 192, k = i % 192;
        float s = gbih[k];
        const float* e = embed + v * Hh;
        const float* w = gwih + k * (2 * Hh);
        #pragma unroll 8
        for (int j = 0; j < Hh; j++) s = fmaf(e[j], w[j], s);
        d_E2[i] = s;
    }
    for (int i = idx; i < Hh * Hh; i += stride) {
        const int a = i >> 6, l = i & 63;
        float s = 0.f;
        for (int t = 0; t < Hh; t++) s = fmaf(kw[t * Hh + a], qw[t * Hh + l], s);
        d_A2[i] = s * 0.125f;
    }
    for (int i = idx; i < Hh; i += stride) {
        float s = 0.f;
        for (int t = 0; t < Hh; t++) s = fmaf(kw[t * Hh + i], qb[t], s);
        d_a0[i] = s * 0.125f;
    }
    for (int i = idx; i < Ll * NBLK; i += stride) d_gpart[i] = 0.f;
}

// ---------------- SMEM layout (float offsets) ----------------
#define OFF_GWHH 0        /* gwhh [k<192][j<64] pad 68 = 13056 (row-major, j-contig) */
#define OFF_E2   13056    /* full E2 table [v<64][k<192] = 12288 */
#define OFF_LWIH 25344    /* lwih [k<128][j<64] pad 68 = 8704 (row-major, j-contig) */
#define OFF_LWHH 34048    /* [j<32][u<32][g<4] = 4096 */
#define OFF_A2   38144    /* A2^T [l][a] = 4096 */
#define OFF_VW   42240    /* vw^T [j][k] = 4096 */
#define OFF_GBHH 46336    /* 192 */
#define OFF_LB2  46528    /* 128 lbih+lbhh */
#define OFF_A0   46656    /* 64 */
#define OFF_VB   46720    /* 64 */
#define OFF_TW   46784    /* 32 */
#define OFF_SC   46816    /* 4 */
#define OFF_HP   46820    /* 8x64 h state (16B-aligned) */
#define OFF_XW   47332    /* ring 4 x 8 x 128 (bias folded) */
#define OFF_GH   51428    /* 8 x 192 */
#define OFF_GI   52964    /* 8 x 192 */
#define OFF_Q2   54500    /* 8x64 */
#define OFF_WS   55012    /* 8x64 */
#define OFF_RET  55524    /* 8x64 */
#define OFF_PROB 56036    /* 8 */
#define OFF_RED  56044    /* 128 */
#define OFF_TOK  56172    /* 2 x 8 ints */
#define SMEM_FLOATS 56188
#define SMEM_BYTES  (SMEM_FLOATS * 4)

__global__ void __launch_bounds__(NT, 1) model_kernel(
    const int*   __restrict__ seq,
    const float* __restrict__ memory,
    const float* __restrict__ gwih,
    const float* __restrict__ gwhh,
    const float* __restrict__ gbhh,
    const float* __restrict__ vw,
    const float* __restrict__ vb,
    const float* __restrict__ lwih,
    const float* __restrict__ lwhh,
    const float* __restrict__ lbih,
    const float* __restrict__ lbhh,
    const float* __restrict__ trigw,
    const float* __restrict__ trigb,
    const float* __restrict__ headw,
    const float* __restrict__ headb,
    float* __restrict__ out,
    int out_size)
{
    extern __shared__ float sm[];
    const int tid = threadIdx.x;
    const int b0  = blockIdx.x * NB;
    int* s_tok = (int*)(sm + OFF_TOK);

    // ---- weight staging ----
    for (int i = tid; i < 192 * 64; i += NT) {           // gwhh row-major, pad 68
        const int k = i >> 6, j = i & 63;
        sm[OFF_GWHH + k * 68 + j] = gwhh[i];
    }
    for (int i = tid; i < 12288; i += NT)                // full E2 table
        sm[OFF_E2 + i] = d_E2[i];
    for (int i = tid; i < 128 * 64; i += NT) {           // lwih row-major, pad 68
        const int k = i >> 6, j = i & 63;
        sm[OFF_LWIH + k * 68 + j] = lwih[i];
    }
    for (int i = tid; i < 4096; i += NT) {               // lwhh [j][u][g]
        const int j = i >> 7, u = (i >> 2) & 31, g = i & 3;
        sm[OFF_LWHH + i] = lwhh[(g * 32 + u) * 32 + j];
    }
    for (int i = tid; i < 4096; i += NT)                 // A2^T [l][a]
        sm[OFF_A2 + i] = d_A2[(i % 64) * 64 + (i / 64)];
    for (int i = tid; i < 4096; i += NT)                 // vw^T [j][k]
        sm[OFF_VW + i] = vw[(i % 64) * 64 + (i / 64)];
    for (int i = tid; i < 192; i += NT) sm[OFF_GBHH + i] = gbhh[i];
    for (int i = tid; i < 128; i += NT) sm[OFF_LB2 + i] = lbih[i] + lbhh[i];
    for (int i = tid; i < 64; i += NT)  { sm[OFF_A0 + i] = d_a0[i]; sm[OFF_VB + i] = vb[i]; }
    for (int i = tid; i < 32; i += NT)  sm[OFF_TW + i] = trigw[i];
    if (tid == 0) sm[OFF_SC] = trigb[0];
    for (int i = tid; i < NB * Hh; i += NT) sm[OFF_HP + i] = 0.f;
    for (int i = tid; i < 1536; i += NT) sm[OFF_GH + i] = gbhh[i % 192];   // gh for t=0 (h=0)
    if (tid < NB) s_tok[tid] = seq[(b0 + tid) * Ll + 0];                    // tokens t=0 -> slot 0
    __syncthreads();

    int read_prev = 0;
    int nreads = 0;

    for (int t = 0; t < Ll; t++) {
        // ===== B: GRU combine -> new h =====
        #pragma unroll
        for (int it = tid; it < NB * Hh; it += NT) {
            const int b = it >> 6, k = it & 63;
            const int tok = s_tok[(t & 1) * 8 + b];
            float gi_r = sm[OFF_E2 + tok * 192 + k];
            float gi_z = sm[OFF_E2 + tok * 192 + 64 + k];
            float gi_n = sm[OFF_E2 + tok * 192 + 128 + k];
            if (read_prev) {
                gi_r += sm[OFF_GI + b * 192 + k];
                gi_z += sm[OFF_GI + b * 192 + 64 + k];
                gi_n += sm[OFF_GI + b * 192 + 128 + k];
            }
            const float gh_r = sm[OFF_GH + b * 192 + k];
            const float gh_z = sm[OFF_GH + b * 192 + 64 + k];
            const float gh_n = sm[OFF_GH + b * 192 + 128 + k];
            const float r = sigf(gi_r + gh_r);
            const float z = sigf(gi_z + gh_z);
            const float n = tanhfast(fmaf(r, gh_n, gi_n));
            const float h = sm[OFF_HP + b * 64 + k];
            sm[OFF_HP + b * 64 + k] = n + z * (h - n);   // (1-z)n + z h
        }
        __syncthreads();   // s1

        // LSTM carry registers (warps 4-7), persist X -> Y (4 scalars only)
        float hh0 = 0.f, hh1 = 0.f, cc0 = 0.f, cc1 = 0.f;

        // ===== X: xW_t (warps 0-3, f32x2 8-batch tiles) || LSTM substeps 0-2 (warps 4-7) =====
        if (tid < 128) {
            const int k = tid;
            const ulonglong2* wrow = (const ulonglong2*)&sm[OFF_LWIH + k * 68];
            unsigned long long acc[NB];
            {
                const unsigned long long binit = pack2(sm[OFF_LB2 + k], 0.f);
                #pragma unroll
                for (int b = 0; b < NB; b++) acc[b] = binit;
            }
            #pragma unroll 4
            for (int g = 0; g < 16; g++) {
                const ulonglong2 w2 = wrow[g];
                #pragma unroll
                for (int b = 0; b < NB; b++) {
                    const ulonglong2 h2 = *(const ulonglong2*)&sm[OFF_HP + b * 64 + g * 4];
                    fma2(acc[b], w2.x, h2.x);
                    fma2(acc[b], w2.y, h2.y);
                }
            }
            float* xw = &sm[OFF_XW + (t & 3) * 1024];
            #pragma unroll
            for (int b = 0; b < NB; b++) {
                float lo, hi;
                unpack2(acc[b], lo, hi);
                xw[b * 128 + k] = lo + hi;
            }
        } else if (t >= 3) {
            // LSTM substeps 0-2: 2 batches/warp, lane owns units (u0, u0+16)
            const int l_lane = tid & 31;
            const int l_half = l_lane >> 4;
            const int l_bb   = ((tid >> 5) - 4) * 2 + l_half;
            const int l_u0   = l_lane & 15;
            {   // substep 0 (no recurrence)
                const float* xw = &sm[OFF_XW + ((t + 1) & 3) * 1024 + l_bb * 128];
                const float gI0 = xw[l_u0],      gG0 = xw[64 + l_u0], gO0 = xw[96 + l_u0];
                const float gI1 = xw[16 + l_u0], gG1 = xw[80 + l_u0], gO1 = xw[112 + l_u0];
                cc0 = sigf(gI0) * tanhfast(gG0);
                cc1 = sigf(gI1) * tanhfast(gG1);
                hh0 = sigf(gO0) * tanhfast(cc0);
                hh1 = sigf(gO1) * tanhfast(cc1);
            }
            #pragma unroll 1
            for (int s = 1; s < 3; s++) {
                const int slot = (t + 1 + s) & 3;
                const float* xw = &sm[OFF_XW + slot * 1024 + l_bb * 128];
                float gI0 = xw[l_u0],      gF0 = xw[32 + l_u0],
                      gG0 = xw[64 + l_u0], gO0 = xw[96 + l_u0];
                float gI1 = xw[16 + l_u0],      gF1 = xw[48 + l_u0],
                      gG1 = xw[80 + l_u0],      gO1 = xw[112 + l_u0];
                #pragma unroll
                for (int j = 0; j < 32; j++) {
                    const float hj = __shfl_sync(0xffffffffu,
                                                 (j < 16) ? hh0 : hh1,
                                                 (l_half << 4) + (j & 15));
                    const float4 w0 = *(const float4*)&sm[OFF_LWHH + (j * 32 + l_u0) * 4];
                    const float4 w1 = *(const float4*)&sm[OFF_LWHH + (j * 32 + l_u0 + 16) * 4];
                    gI0 = fmaf(w0.x, hj, gI0); gF0 = fmaf(w0.y, hj, gF0);
                    gG0 = fmaf(w0.z, hj, gG0); gO0 = fmaf(w0.w, hj, gO0);
                    gI1 = fmaf(w1.x, hj, gI1); gF1 = fmaf(w1.y, hj, gF1);
                    gG1 = fmaf(w1.z, hj, gG1); gO1 = fmaf(w1.w, hj, gO1);
                }
                const float c0 = fmaf(sigf(gF0), cc0, sigf(gI0) * tanhfast(gG0));
                const float c1 = fmaf(sigf(gF1), cc1, sigf(gI1) * tanhfast(gG1));
                cc0 = c0; hh0 = sigf(gO0) * tanhfast(c0);
                cc1 = c1; hh1 = sigf(gO1) * tanhfast(c1);
            }
        }
        __syncthreads();   // s2

        // ===== Y: gh_{t+1} k<128 (warps 0-3) || LSTM substep 3 + prob (warps 4-7) =====
        if (tid < 128) {
            const int k = tid;
            const ulonglong2* wrow = (const ulonglong2*)&sm[OFF_GWHH + k * 68];
            unsigned long long acc[NB];
            {
                const unsigned long long binit = pack2(sm[OFF_GBHH + k], 0.f);
                #pragma unroll
                for (int b = 0; b < NB; b++) acc[b] = binit;
            }
            #pragma unroll 4
            for (int g = 0; g < 16; g++) {
                const ulonglong2 w2 = wrow[g];
                #pragma unroll
                for (int b = 0; b < NB; b++) {
                    const ulonglong2 h2 = *(const ulonglong2*)&sm[OFF_HP + b * 64 + g * 4];
                    fma2(acc[b], w2.x, h2.x);
                    fma2(acc[b], w2.y, h2.y);
                }
            }
            #pragma unroll
            for (int b = 0; b < NB; b++) {
                float lo, hi;
                unpack2(acc[b], lo, hi);
                sm[OFF_GH + b * 192 + k] = lo + hi;
            }
        } else if (t >= 3) {
            const int l_lane = tid & 31;
            const int l_half = l_lane >> 4;
            const int l_bb   = ((tid >> 5) - 4) * 2 + l_half;
            const int l_u0   = l_lane & 15;
            const int slot = t & 3;
            const float* xw = &sm[OFF_XW + slot * 1024 + l_bb * 128];
            float gI0 = xw[l_u0],      gF0 = xw[32 + l_u0],
                  gG0 = xw[64 + l_u0], gO0 = xw[96 + l_u0];
            float gI1 = xw[16 + l_u0],      gF1 = xw[48 + l_u0],
                  gG1 = xw[80 + l_u0],      gO1 = xw[112 + l_u0];
            #pragma unroll
            for (int j = 0; j < 32; j++) {
                const float hj = __shfl_sync(0xffffffffu,
                                             (j < 16) ? hh0 : hh1,
                                             (l_half << 4) + (j & 15));
                const float4 w0 = *(const float4*)&sm[OFF_LWHH + (j * 32 + l_u0) * 4];
                const float4 w1 = *(const float4*)&sm[OFF_LWHH + (j * 32 + l_u0 + 16) * 4];
                gI0 = fmaf(w0.x, hj, gI0); gF0 = fmaf(w0.y, hj, gF0);
                gG0 = fmaf(w0.z, hj, gG0); gO0 = fmaf(w0.w, hj, gO0);
                gI1 = fmaf(w1.x, hj, gI1); gF1 = fmaf(w1.y, hj, gF1);
                gG1 = fmaf(w1.z, hj, gG1); gO1 = fmaf(w1.w, hj, gO1);
            }
            const float c0 = fmaf(sigf(gF0), cc0, sigf(gI0) * tanhfast(gG0));
            const float c1 = fmaf(sigf(gF1), cc1, sigf(gI1) * tanhfast(gG1));
            const float hf0 = sigf(gO0) * tanhfast(c0);
            const float hf1 = sigf(gO1) * tanhfast(c1);
            float v = hf0 * sm[OFF_TW + l_u0] + hf1 * sm[OFF_TW + l_u0 + 16];
            #pragma unroll
            for (int o = 8; o > 0; o >>= 1) v += __shfl_xor_sync(0xffffffffu, v, o);
            if (l_u0 == 0) sm[OFF_PROB + l_bb] = sigf(v + sm[OFF_SC]);
        }
        __syncthreads();   // s3

        // ===== Z: gh k in [128,192) (threads 0-63) || tokens || post+poll (192-255) =====
        if (tid < 64) {
            const int k = 128 + tid;
            const ulonglong2* wrow = (const ulonglong2*)&sm[OFF_GWHH + k * 68];
            unsigned long long acc[NB];
            {
                const unsigned long long binit = pack2(sm[OFF_GBHH + k], 0.f);
                #pragma unroll
                for (int b = 0; b < NB; b++) acc[b] = binit;
            }
            #pragma unroll 4
            for (int g = 0; g < 16; g++) {
                const ulonglong2 w2 = wrow[g];
                #pragma unroll
                for (int b = 0; b < NB; b++) {
                    const ulonglong2 h2 = *(const ulonglong2*)&sm[OFF_HP + b * 64 + g * 4];
                    fma2(acc[b], w2.x, h2.x);
                    fma2(acc[b], w2.y, h2.y);
                }
            }
            #pragma unroll
            for (int b = 0; b < NB; b++) {
                float lo, hi;
                unpack2(acc[b], lo, hi);
                sm[OFF_GH + b * 192 + k] = lo + hi;
            }
        } else if (tid >= 64 && tid < 72) {
            if (t + 1 < Ll)
                s_tok[((t + 1) & 1) * 8 + (tid - 64)] = seq[(b0 + tid - 64) * Ll + (t + 1)];
        } else if (tid >= 192 && t >= 3) {
            const int i = tid - 192;                      // 64 pollers, 2 slots each
            if (i == 0) {                                 // poster
                float pv = sm[OFF_PROB + 0] + sm[OFF_PROB + 1] + sm[OFF_PROB + 2] + sm[OFF_PROB + 3]
                         + sm[OFF_PROB + 4] + sm[OFF_PROB + 5] + sm[OFF_PROB + 6] + sm[OFF_PROB + 7];
                asm volatile("st.global.cg.f32 [%0], %1;"
                             :: "l"(&d_gpart[t * NBLK + blockIdx.x]), "f"(pv + 1.f)
                             : "memory");
            }
            const float* g0 = &d_gpart[t * NBLK + i];
            const float* g1 = &d_gpart[t * NBLK + 64 + i];
            float v0, v1;
            do {
                asm volatile("ld.global.cg.f32 %0, [%1];" : "=f"(v0) : "l"(g0) : "memory");
            } while (v0 == 0.f);
            do {
                asm volatile("ld.global.cg.f32 %0, [%1];" : "=f"(v1) : "l"(g1) : "memory");
            } while (v1 == 0.f);
            sm[OFF_RED + i]      = v0 - 1.f;
            sm[OFF_RED + 64 + i] = v1 - 1.f;
        }
        __syncthreads();   // s4

        if (t >= 3) {
            // every warp reduces redundantly -> uniform do_read in registers
            const int ln = tid & 31;
            float s = sm[OFF_RED + ln] + sm[OFF_RED + 32 + ln]
                    + sm[OFF_RED + 64 + ln] + sm[OFF_RED + 96 + ln];
            #pragma unroll
            for (int o = 16; o > 0; o >>= 1) s += __shfl_xor_sync(0xffffffffu, s, o);
            const int do_read = (s > 512.f);

            if (do_read) {
                // ---- attention: q2 = A2 h + a0 ----
                if (tid < 64) {
                    const int k = tid;
                    float acc[NB];
                    #pragma unroll
                    for (int b = 0; b < NB; b++) acc[b] = sm[OFF_A0 + k];
                    #pragma unroll 4
                    for (int j = 0; j < 64; j += 4) {
                        const float w0 = sm[OFF_A2 + (j + 0) * 64 + k];
                        const float w1 = sm[OFF_A2 + (j + 1) * 64 + k];
                        const float w2 = sm[OFF_A2 + (j + 2) * 64 + k];
                        const float w3 = sm[OFF_A2 + (j + 3) * 64 + k];
                        #pragma unroll
                        for (int b = 0; b < NB; b++) {
                            const float4 h4 = *(const float4*)&sm[OFF_HP + b * 64 + j];
                            acc[b] = fmaf(w0, h4.x, acc[b]);
                            acc[b] = fmaf(w1, h4.y, acc[b]);
                            acc[b] = fmaf(w2, h4.z, acc[b]);
                            acc[b] = fmaf(w3, h4.w, acc[b]);
                        }
                    }
                    #pragma unroll
                    for (int b = 0; b < NB; b++) sm[OFF_Q2 + b * 64 + k] = acc[b];
                }
                __syncthreads();
                {   // streaming online softmax over memory (warp per batch)
                    const int w2 = tid >> 5, l2 = tid & 31;
                    const float* mb = memory + (size_t)(b0 + w2) * (Mm * Hh);
                    const float q0 = sm[OFF_Q2 + w2 * 64 + 2 * l2];
                    const float q1 = sm[OFF_Q2 + w2 * 64 + 2 * l2 + 1];
                    float mx = -3.0e38f, dn = 0.f, ra = 0.f, rb = 0.f;
                    #pragma unroll 4
                    for (int m = 0; m < Mm; m++) {
                        const float2 mmv = *(const float2*)(mb + m * 64 + 2 * l2);
                        float p = q0 * mmv.x + q1 * mmv.y;
                        #pragma unroll
                        for (int o = 16; o > 0; o >>= 1) p += __shfl_xor_sync(0xffffffffu, p, o);
                        const float nm = fmaxf(mx, p);
                        const float f  = __expf(mx - nm);
                        const float e  = __expf(p - nm);
                        dn = fmaf(dn, f, e);
                        ra = fmaf(ra, f, e * mmv.x);
                        rb = fmaf(rb, f, e * mmv.y);
                        mx = nm;
                    }
                    const float inv = 1.f / dn;
                    sm[OFF_WS + w2 * 64 + 2 * l2]     = ra * inv;
                    sm[OFF_WS + w2 * 64 + 2 * l2 + 1] = rb * inv;
                }
                __syncthreads();
                if (tid < 64) {   // retrieved = v_w ws + v_b
                    const int k = tid;
                    float acc[NB];
                    #pragma unroll
                    for (int b = 0; b < NB; b++) acc[b] = sm[OFF_VB + k];
                    #pragma unroll 4
                    for (int j = 0; j < 64; j += 4) {
                        const float w0 = sm[OFF_VW + (j + 0) * 64 + k];
                        const float w1 = sm[OFF_VW + (j + 1) * 64 + k];
                        const float w2 = sm[OFF_VW + (j + 2) * 64 + k];
                        const float w3 = sm[OFF_VW + (j + 3) * 64 + k];
                        #pragma unroll
                        for (int b = 0; b < NB; b++) {
                            const float4 s4 = *(const float4*)&sm[OFF_WS + b * 64 + j];
                            acc[b] = fmaf(w0, s4.x, acc[b]);
                            acc[b] = fmaf(w1, s4.y, acc[b]);
                            acc[b] = fmaf(w2, s4.z, acc[b]);
                            acc[b] = fmaf(w3, s4.w, acc[b]);
                        }
                    }
                    #pragma unroll
                    for (int b = 0; b < NB; b++) sm[OFF_RET + b * 64 + k] = acc[b];
                }
                __syncthreads();
                // GI = Wr . retrieved  (Wr read from global — rare path)
                if (tid < 192) {
                    const int k = tid;
                    float acc[NB];
                    #pragma unroll
                    for (int b = 0; b < NB; b++) acc[b] = 0.f;
                    const float* wr = &gwih[k * 128 + 64];
                    #pragma unroll 4
                    for (int j = 0; j < 64; j += 4) {
                        const float4 w4 = __ldg((const float4*)(wr + j));
                        #pragma unroll
                        for (int b = 0; b < NB; b++) {
                            const float4 r4 = *(const float4*)&sm[OFF_RET + b * 64 + j];
                            acc[b] = fmaf(w4.x, r4.x, acc[b]);
                            acc[b] = fmaf(w4.y, r4.y, acc[b]);
                            acc[b] = fmaf(w4.z, r4.z, acc[b]);
                            acc[b] = fmaf(w4.w, r4.w, acc[b]);
                        }
                    }
                    #pragma unroll
                    for (int b = 0; b < NB; b++) sm[OFF_GI + b * 192 + k] = acc[b];
                }
                __syncthreads();   // protect GI before next-step B
                nreads++;
            }
            read_prev = do_read;
        } else {
            read_prev = 0;
        }
        // next-step B (writes HP) is safe: all HP readers finished before s4
    }

    __syncthreads();
    // ---------- epilogue: logits = h @ head_w^T + head_b ----------
    if (tid < 64) {
        const int k = tid;
        float acc[NB];
        const float hb = __ldg(&headb[k]);
        #pragma unroll
        for (int b = 0; b < NB; b++) acc[b] = hb;
        #pragma unroll 4
        for (int j = 0; j < 64; j += 4) {
            const float4 w4 = __ldg((const float4*)(headw + k * 64 + j));
            #pragma unroll
            for (int b = 0; b < NB; b++) {
                const float4 h4 = *(const float4*)&sm[OFF_HP + b * 64 + j];
                acc[b] = fmaf(w4.x, h4.x, acc[b]);
                acc[b] = fmaf(w4.y, h4.y, acc[b]);
                acc[b] = fmaf(w4.z, h4.z, acc[b]);
                acc[b] = fmaf(w4.w, h4.w, acc[b]);
            }
        }
        #pragma unroll
        for (int b = 0; b < NB; b++) out[(size_t)(b0 + b) * Vv + k] = acc[b];
    }
    if (blockIdx.x == 0 && tid == 0) {
        const float rr = (float)nreads * (1.f / (float)Ll);
        for (int i = Bb * Vv; i < out_size; i++) out[i] = rr;
    }
}

extern "C" void kernel_launch(void* const* d_in, const int* in_sizes, int n_in,
                              void* d_out, int out_size) {
    const int*   seq    = (const int*)  d_in[0];
    const float* memory = (const float*)d_in[1];
    const float* embed  = (const float*)d_in[2];
    const float* gwih   = (const float*)d_in[3];
    const float* gwhh   = (const float*)d_in[4];
    const float* gbih   = (const float*)d_in[5];
    const float* gbhh   = (const float*)d_in[6];
    const float* qw     = (const float*)d_in[7];
    const float* qb     = (const float*)d_in[8];
    const float* kw     = (const float*)d_in[9];
    /* k_b (d_in[10]) cancels in softmax — unused */
    const float* vw     = (const float*)d_in[11];
    const float* vb     = (const float*)d_in[12];
    const float* lwih   = (const float*)d_in[13];
    const float* lwhh   = (const float*)d_in[14];
    const float* lbih   = (const float*)d_in[15];
    const float* lbhh   = (const float*)d_in[16];
    const float* trigw  = (const float*)d_in[17];
    const float* trigb  = (const float*)d_in[18];
    const float* headw  = (const float*)d_in[19];
    const float* headb  = (const float*)d_in[20];
    float* out = (float*)d_out;

    cudaFuncSetAttribute(model_kernel,
                         cudaFuncAttributeMaxDynamicSharedMemorySize, SMEM_BYTES);

    prep_kernel<<<64, 256>>>(embed, gwih, gbih, kw, qw, qb);
    model_kernel<<<NBLK, NT, SMEM_BYTES>>>(seq, memory, gwih, gwhh, gbhh,
                                           vw, vb, lwih, lwhh, lbih, lbhh,
                                           trigw, trigb, headw, headb,
                                           out, out_size);
}

// round 12
// speedup vs baseline: 1.3124x; 1.0826x over previous
#include <cuda_runtime.h>
#include <math.h>

#define Bb   1024
#define Ll   256
#define Mm   256
#define Hh   64
#define Vv   64
#define NB   8      // batches per block
#define NBLK 128
#define NT   256

// ---------------- device scratch ----------------
__device__ float d_E2[Vv * 192];       // embed @ Wx^T + b_ih   (64 x 192)
__device__ float d_A2[Hh * Hh];        // (q_w^T k_w) / 8  stored [a][l]
__device__ float d_a0[Hh];             // (q_b^T k_w) / 8
__device__ float d_gpart[Ll * NBLK];   // per-step per-block partial sums (+1.0 sentinel)

__device__ __forceinline__ float sigf(float x)     { return 1.f / (1.f + __expf(-x)); }
__device__ __forceinline__ float tanhfast(float x) { return 2.f / (1.f + __expf(-2.f * x)) - 1.f; }

__device__ __forceinline__ unsigned long long pack2(float a, float b) {
    unsigned long long r;
    asm("mov.b64 %0, {%1, %2};" : "=l"(r) : "f"(a), "f"(b));
    return r;
}
__device__ __forceinline__ void unpack2(unsigned long long v, float& a, float& b) {
    asm("mov.b64 {%0, %1}, %2;" : "=f"(a), "=f"(b) : "l"(v));
}
__device__ __forceinline__ void fma2(unsigned long long& d, unsigned long long a, unsigned long long b) {
    asm("fma.rn.f32x2 %0, %1, %2, %0;" : "+l"(d) : "l"(a), "l"(b));
}

// ---------------- prep ----------------
__global__ void prep_kernel(const float* __restrict__ embed,
                            const float* __restrict__ gwih,
                            const float* __restrict__ gbih,
                            const float* __restrict__ kw,
                            const float* __restrict__ qw,
                            const float* __restrict__ qb) {
    const int idx = blockIdx.x * blockDim.x + threadIdx.x;
    const int stride = gridDim.x * blockDim.x;
    for (int i = idx; i < Vv * 192; i += stride) {
        const int v = i / 192, k = i % 192;
        float s = gbih[k];
        const float* e = embed + v * Hh;
        const float* w = gwih + k * (2 * Hh);
        #pragma unroll 8
        for (int j = 0; j < Hh; j++) s = fmaf(e[j], w[j], s);
        d_E2[i] = s;
    }
    for (int i = idx; i < Hh * Hh; i += stride) {
        const int a = i >> 6, l = i & 63;
        float s = 0.f;
        for (int t = 0; t < Hh; t++) s = fmaf(kw[t * Hh + a], qw[t * Hh + l], s);
        d_A2[i] = s * 0.125f;
    }
    for (int i = idx; i < Hh; i += stride) {
        float s = 0.f;
        for (int t = 0; t < Hh; t++) s = fmaf(kw[t * Hh + i], qb[t], s);
        d_a0[i] = s * 0.125f;
    }
    for (int i = idx; i < Ll * NBLK; i += stride) d_gpart[i] = 0.f;
}

// ---------------- SMEM layout (float offsets) ----------------
#define OFF_GWHH 0        /* gwhh [k<192][j<64] pad 68 = 13056 */
#define OFF_E2   13056    /* E2 table [v<64][k<192] = 12288 */
#define OFF_LWIH 25344    /* lwih [j<64][u<32][g<4] = 8192 */
#define OFF_LWHH 33536    /* lwhh [j<32][u<32][g<4] = 4096 */
#define OFF_A2   37632    /* A2^T [l][a] = 4096 */
#define OFF_VW   41728    /* vw^T [j][k] = 4096 */
#define OFF_GBHH 45824    /* 192 */
#define OFF_LB2  46016    /* 128 lbih+lbhh */
#define OFF_A0   46144    /* 64 */
#define OFF_VB   46208    /* 64 */
#define OFF_TW   46272    /* 32 */
#define OFF_SC   46304    /* 4 */
#define OFF_HP   46308    /* 8x64 h state (16B-aligned) */
#define OFF_XW   46820    /* ring 4 x 8 x 128 (bias folded) */
#define OFF_GH   50916    /* 8 x 192 */
#define OFF_GI   52452    /* 8 x 192 */
#define OFF_Q2   53988    /* 8x64 */
#define OFF_WS   54500    /* 8x64 */
#define OFF_RET  55012    /* 8x64 */
#define OFF_PROB 55524    /* 8 */
#define OFF_RED  55532    /* 128 */
#define OFF_TOK  55660    /* 2 x 8 ints */
#define SMEM_FLOATS 55676
#define SMEM_BYTES  (SMEM_FLOATS * 4)

__global__ void __launch_bounds__(NT, 1) model_kernel(
    const int*   __restrict__ seq,
    const float* __restrict__ memory,
    const float* __restrict__ gwih,
    const float* __restrict__ gwhh,
    const float* __restrict__ gbhh,
    const float* __restrict__ vw,
    const float* __restrict__ vb,
    const float* __restrict__ lwih,
    const float* __restrict__ lwhh,
    const float* __restrict__ lbih,
    const float* __restrict__ lbhh,
    const float* __restrict__ trigw,
    const float* __restrict__ trigb,
    const float* __restrict__ headw,
    const float* __restrict__ headb,
    float* __restrict__ out,
    int out_size)
{
    extern __shared__ float sm[];
    const int tid = threadIdx.x;
    const int b0  = blockIdx.x * NB;
    int* s_tok = (int*)(sm + OFF_TOK);

    // ---- weight staging ----
    for (int i = tid; i < 192 * 64; i += NT) {           // gwhh row-major, pad 68
        const int k = i >> 6, j = i & 63;
        sm[OFF_GWHH + k * 68 + j] = gwhh[i];
    }
    for (int i = tid; i < 12288; i += NT)                // E2 table
        sm[OFF_E2 + i] = d_E2[i];
    for (int i = tid; i < 8192; i += NT) {               // lwih [j][u][g]
        const int j = i >> 7, u = (i >> 2) & 31, g = i & 3;
        sm[OFF_LWIH + i] = lwih[(g * 32 + u) * 64 + j];
    }
    for (int i = tid; i < 4096; i += NT) {               // lwhh [j][u][g]
        const int j = i >> 7, u = (i >> 2) & 31, g = i & 3;
        sm[OFF_LWHH + i] = lwhh[(g * 32 + u) * 32 + j];
    }
    for (int i = tid; i < 4096; i += NT)                 // A2^T [l][a]
        sm[OFF_A2 + i] = d_A2[(i % 64) * 64 + (i / 64)];
    for (int i = tid; i < 4096; i += NT)                 // vw^T [j][k]
        sm[OFF_VW + i] = vw[(i % 64) * 64 + (i / 64)];
    for (int i = tid; i < 192; i += NT) sm[OFF_GBHH + i] = gbhh[i];
    for (int i = tid; i < 128; i += NT) sm[OFF_LB2 + i] = lbih[i] + lbhh[i];
    for (int i = tid; i < 64; i += NT)  { sm[OFF_A0 + i] = d_a0[i]; sm[OFF_VB + i] = vb[i]; }
    for (int i = tid; i < 32; i += NT)  sm[OFF_TW + i] = trigw[i];
    if (tid == 0) sm[OFF_SC] = trigb[0];
    for (int i = tid; i < NB * Hh; i += NT) sm[OFF_HP + i] = 0.f;
    for (int i = tid; i < 1536; i += NT) sm[OFF_GH + i] = gbhh[i % 192];   // gh for t=0 (h=0)
    if (tid < NB) s_tok[tid] = seq[(b0 + tid) * Ll + 0];
    __syncthreads();

    int read_prev = 0;
    int nreads = 0;

    const int w = tid >> 5;   // this warp's batch
    const int u = tid & 31;   // this lane's LSTM unit / k offset

    for (int t = 0; t < Ll; t++) {
        // ===== W: warp-private per-batch chain (combine -> xW -> LSTM -> prob) =====
        {
            // -- GRU combine for batch w, units u and u+32 --
            const int tok = s_tok[(t & 1) * 8 + w];
            #pragma unroll
            for (int kk = 0; kk < 2; kk++) {
                const int k = u + kk * 32;
                float gi_r = sm[OFF_E2 + tok * 192 + k];
                float gi_z = sm[OFF_E2 + tok * 192 + 64 + k];
                float gi_n = sm[OFF_E2 + tok * 192 + 128 + k];
                if (read_prev) {
                    gi_r += sm[OFF_GI + w * 192 + k];
                    gi_z += sm[OFF_GI + w * 192 + 64 + k];
                    gi_n += sm[OFF_GI + w * 192 + 128 + k];
                }
                const float gh_r = sm[OFF_GH + w * 192 + k];
                const float gh_z = sm[OFF_GH + w * 192 + 64 + k];
                const float gh_n = sm[OFF_GH + w * 192 + 128 + k];
                const float r = sigf(gi_r + gh_r);
                const float z = sigf(gi_z + gh_z);
                const float n = tanhfast(fmaf(r, gh_n, gi_n));
                const float h = sm[OFF_HP + w * 64 + k];
                sm[OFF_HP + w * 64 + k] = n + z * (h - n);
            }
            __syncwarp();

            // -- xW_t for batch w: lane u computes gates (i,f,g,o) of unit u --
            float4 ag;
            ag.x = sm[OFF_LB2 + u];
            ag.y = sm[OFF_LB2 + 32 + u];
            ag.z = sm[OFF_LB2 + 64 + u];
            ag.w = sm[OFF_LB2 + 96 + u];
            const float2 h2 = *(const float2*)&sm[OFF_HP + w * 64 + 2 * u];
            #pragma unroll
            for (int j2 = 0; j2 < 32; j2++) {
                const float hx = __shfl_sync(0xffffffffu, h2.x, j2);
                const float hy = __shfl_sync(0xffffffffu, h2.y, j2);
                const float4 w0 = *(const float4*)&sm[OFF_LWIH + ((2 * j2) * 32 + u) * 4];
                const float4 w1 = *(const float4*)&sm[OFF_LWIH + ((2 * j2 + 1) * 32 + u) * 4];
                ag.x = fmaf(w0.x, hx, ag.x); ag.y = fmaf(w0.y, hx, ag.y);
                ag.z = fmaf(w0.z, hx, ag.z); ag.w = fmaf(w0.w, hx, ag.w);
                ag.x = fmaf(w1.x, hy, ag.x); ag.y = fmaf(w1.y, hy, ag.y);
                ag.z = fmaf(w1.z, hy, ag.z); ag.w = fmaf(w1.w, hy, ag.w);
            }
            {   // ring write (future steps, same warp)
                float* xw = &sm[OFF_XW + (t & 3) * 1024 + w * 128];
                xw[u]      = ag.x;
                xw[32 + u] = ag.y;
                xw[64 + u] = ag.z;
                xw[96 + u] = ag.w;
            }

            // -- trigger LSTM over hist (warp-private ring), prob --
            if (t >= 3) {
                float hh, cc;
                {   // substep 0 (no recurrence), slot (t+1)&3
                    const float* x0 = &sm[OFF_XW + ((t + 1) & 3) * 1024 + w * 128];
                    const float gI = x0[u], gG = x0[64 + u], gO = x0[96 + u];
                    cc = sigf(gI) * tanhfast(gG);
                    hh = sigf(gO) * tanhfast(cc);
                }
                #pragma unroll 1
                for (int s = 1; s < 3; s++) {
                    const float* xs = &sm[OFF_XW + ((t + 1 + s) & 3) * 1024 + w * 128];
                    float gI = xs[u], gF = xs[32 + u], gG = xs[64 + u], gO = xs[96 + u];
                    #pragma unroll
                    for (int j = 0; j < 32; j++) {
                        const float hj = __shfl_sync(0xffffffffu, hh, j);
                        const float4 wv = *(const float4*)&sm[OFF_LWHH + (j * 32 + u) * 4];
                        gI = fmaf(wv.x, hj, gI); gF = fmaf(wv.y, hj, gF);
                        gG = fmaf(wv.z, hj, gG); gO = fmaf(wv.w, hj, gO);
                    }
                    const float c = fmaf(sigf(gF), cc, sigf(gI) * tanhfast(gG));
                    cc = c; hh = sigf(gO) * tanhfast(c);
                }
                {   // substep 3: gates straight from ag registers (xW_t)
                    float gI = ag.x, gF = ag.y, gG = ag.z, gO = ag.w;
                    #pragma unroll
                    for (int j = 0; j < 32; j++) {
                        const float hj = __shfl_sync(0xffffffffu, hh, j);
                        const float4 wv = *(const float4*)&sm[OFF_LWHH + (j * 32 + u) * 4];
                        gI = fmaf(wv.x, hj, gI); gF = fmaf(wv.y, hj, gF);
                        gG = fmaf(wv.z, hj, gG); gO = fmaf(wv.w, hj, gO);
                    }
                    const float c  = fmaf(sigf(gF), cc, sigf(gI) * tanhfast(gG));
                    const float hf = sigf(gO) * tanhfast(c);
                    float v = hf * sm[OFF_TW + u];
                    #pragma unroll
                    for (int o = 16; o > 0; o >>= 1) v += __shfl_xor_sync(0xffffffffu, v, o);
                    if (u == 0) sm[OFF_PROB + w] = sigf(v + sm[OFF_SC]);
                }
            }
        }
        __syncthreads();   // s1: HP + PROB ready

        // ===== E: gh_{t+1} (threads 0-191, f32x2 8-batch tiles) || tokens + post + poll =====
        if (tid < 192) {
            const int k = tid;
            const ulonglong2* wrow = (const ulonglong2*)&sm[OFF_GWHH + k * 68];
            unsigned long long acc[NB];
            {
                const unsigned long long binit = pack2(sm[OFF_GBHH + k], 0.f);
                #pragma unroll
                for (int b = 0; b < NB; b++) acc[b] = binit;
            }
            #pragma unroll 4
            for (int g = 0; g < 16; g++) {
                const ulonglong2 w2 = wrow[g];
                #pragma unroll
                for (int b = 0; b < NB; b++) {
                    const ulonglong2 h2 = *(const ulonglong2*)&sm[OFF_HP + b * 64 + g * 4];
                    fma2(acc[b], w2.x, h2.x);
                    fma2(acc[b], w2.y, h2.y);
                }
            }
            #pragma unroll
            for (int b = 0; b < NB; b++) {
                float lo, hi;
                unpack2(acc[b], lo, hi);
                sm[OFF_GH + b * 192 + k] = lo + hi;
            }
        } else {
            const int i = tid - 192;                      // 64 threads
            if (i < 8 && t + 1 < Ll)
                s_tok[((t + 1) & 1) * 8 + i] = seq[(b0 + i) * Ll + (t + 1)];
            if (t >= 3) {
                if (i == 0) {                             // poster
                    float pv = sm[OFF_PROB + 0] + sm[OFF_PROB + 1] + sm[OFF_PROB + 2] + sm[OFF_PROB + 3]
                             + sm[OFF_PROB + 4] + sm[OFF_PROB + 5] + sm[OFF_PROB + 6] + sm[OFF_PROB + 7];
                    asm volatile("st.global.cg.f32 [%0], %1;"
                                 :: "l"(&d_gpart[t * NBLK + blockIdx.x]), "f"(pv + 1.f)
                                 : "memory");
                }
                const float* g0 = &d_gpart[t * NBLK + i];
                const float* g1 = &d_gpart[t * NBLK + 64 + i];
                float v0, v1;
                do {
                    asm volatile("ld.global.cg.f32 %0, [%1];" : "=f"(v0) : "l"(g0) : "memory");
                } while (v0 == 0.f);
                do {
                    asm volatile("ld.global.cg.f32 %0, [%1];" : "=f"(v1) : "l"(g1) : "memory");
                } while (v1 == 0.f);
                sm[OFF_RED + i]      = v0 - 1.f;
                sm[OFF_RED + 64 + i] = v1 - 1.f;
            }
        }
        __syncthreads();   // s2: gh + RED ready

        if (t >= 3) {
            // every warp reduces redundantly -> uniform do_read in registers
            float s = sm[OFF_RED + u] + sm[OFF_RED + 32 + u]
                    + sm[OFF_RED + 64 + u] + sm[OFF_RED + 96 + u];
            #pragma unroll
            for (int o = 16; o > 0; o >>= 1) s += __shfl_xor_sync(0xffffffffu, s, o);
            const int do_read = (s > 512.f);

            if (do_read) {
                // ---- attention: q2 = A2 h + a0 ----
                if (tid < 64) {
                    const int k = tid;
                    float acc[NB];
                    #pragma unroll
                    for (int b = 0; b < NB; b++) acc[b] = sm[OFF_A0 + k];
                    #pragma unroll 4
                    for (int j = 0; j < 64; j += 4) {
                        const float w0 = sm[OFF_A2 + (j + 0) * 64 + k];
                        const float w1 = sm[OFF_A2 + (j + 1) * 64 + k];
                        const float w2 = sm[OFF_A2 + (j + 2) * 64 + k];
                        const float w3 = sm[OFF_A2 + (j + 3) * 64 + k];
                        #pragma unroll
                        for (int b = 0; b < NB; b++) {
                            const float4 h4 = *(const float4*)&sm[OFF_HP + b * 64 + j];
                            acc[b] = fmaf(w0, h4.x, acc[b]);
                            acc[b] = fmaf(w1, h4.y, acc[b]);
                            acc[b] = fmaf(w2, h4.z, acc[b]);
                            acc[b] = fmaf(w3, h4.w, acc[b]);
                        }
                    }
                    #pragma unroll
                    for (int b = 0; b < NB; b++) sm[OFF_Q2 + b * 64 + k] = acc[b];
                }
                __syncthreads();
                {   // streaming online softmax over memory (warp per batch)
                    const float* mb = memory + (size_t)(b0 + w) * (Mm * Hh);
                    const float q0 = sm[OFF_Q2 + w * 64 + 2 * u];
                    const float q1 = sm[OFF_Q2 + w * 64 + 2 * u + 1];
                    float mx = -3.0e38f, dn = 0.f, ra = 0.f, rb = 0.f;
                    #pragma unroll 4
                    for (int m = 0; m < Mm; m++) {
                        const float2 mmv = *(const float2*)(mb + m * 64 + 2 * u);
                        float p = q0 * mmv.x + q1 * mmv.y;
                        #pragma unroll
                        for (int o = 16; o > 0; o >>= 1) p += __shfl_xor_sync(0xffffffffu, p, o);
                        const float nm = fmaxf(mx, p);
                        const float f  = __expf(mx - nm);
                        const float e  = __expf(p - nm);
                        dn = fmaf(dn, f, e);
                        ra = fmaf(ra, f, e * mmv.x);
                        rb = fmaf(rb, f, e * mmv.y);
                        mx = nm;
                    }
                    const float inv = 1.f / dn;
                    sm[OFF_WS + w * 64 + 2 * u]     = ra * inv;
                    sm[OFF_WS + w * 64 + 2 * u + 1] = rb * inv;
                }
                __syncthreads();
                if (tid < 64) {   // retrieved = v_w ws + v_b
                    const int k = tid;
                    float acc[NB];
                    #pragma unroll
                    for (int b = 0; b < NB; b++) acc[b] = sm[OFF_VB + k];
                    #pragma unroll 4
                    for (int j = 0; j < 64; j += 4) {
                        const float w0 = sm[OFF_VW + (j + 0) * 64 + k];
                        const float w1 = sm[OFF_VW + (j + 1) * 64 + k];
                        const float w2 = sm[OFF_VW + (j + 2) * 64 + k];
                        const float w3 = sm[OFF_VW + (j + 3) * 64 + k];
                        #pragma unroll
                        for (int b = 0; b < NB; b++) {
                            const float4 s4 = *(const float4*)&sm[OFF_WS + b * 64 + j];
                            acc[b] = fmaf(w0, s4.x, acc[b]);
                            acc[b] = fmaf(w1, s4.y, acc[b]);
                            acc[b] = fmaf(w2, s4.z, acc[b]);
                            acc[b] = fmaf(w3, s4.w, acc[b]);
                        }
                    }
                    #pragma unroll
                    for (int b = 0; b < NB; b++) sm[OFF_RET + b * 64 + k] = acc[b];
                }
                __syncthreads();
                // GI = Wr . retrieved  (Wr read from global — rare path)
                if (tid < 192) {
                    const int k = tid;
                    float acc[NB];
                    #pragma unroll
                    for (int b = 0; b < NB; b++) acc[b] = 0.f;
                    const float* wr = &gwih[k * 128 + 64];
                    #pragma unroll 4
                    for (int j = 0; j < 64; j += 4) {
                        const float4 w4 = __ldg((const float4*)(wr + j));
                        #pragma unroll
                        for (int b = 0; b < NB; b++) {
                            const float4 r4 = *(const float4*)&sm[OFF_RET + b * 64 + j];
                            acc[b] = fmaf(w4.x, r4.x, acc[b]);
                            acc[b] = fmaf(w4.y, r4.y, acc[b]);
                            acc[b] = fmaf(w4.z, r4.z, acc[b]);
                            acc[b] = fmaf(w4.w, r4.w, acc[b]);
                        }
                    }
                    #pragma unroll
                    for (int b = 0; b < NB; b++) sm[OFF_GI + b * 192 + k] = acc[b];
                }
                __syncthreads();   // protect GI before next-step W
                nreads++;
            }
            read_prev = do_read;
        } else {
            read_prev = 0;
        }
    }

    __syncthreads();
    // ---------- epilogue: logits = h @ head_w^T + head_b ----------
    if (tid < 64) {
        const int k = tid;
        float acc[NB];
        const float hb = __ldg(&headb[k]);
        #pragma unroll
        for (int b = 0; b < NB; b++) acc[b] = hb;
        #pragma unroll 4
        for (int j = 0; j < 64; j += 4) {
            const float4 w4 = __ldg((const float4*)(headw + k * 64 + j));
            #pragma unroll
            for (int b = 0; b < NB; b++) {
                const float4 h4 = *(const float4*)&sm[OFF_HP + b * 64 + j];
                acc[b] = fmaf(w4.x, h4.x, acc[b]);
                acc[b] = fmaf(w4.y, h4.y, acc[b]);
                acc[b] = fmaf(w4.z, h4.z, acc[b]);
                acc[b] = fmaf(w4.w, h4.w, acc[b]);
            }
        }
        #pragma unroll
        for (int b = 0; b < NB; b++) out[(size_t)(b0 + b) * Vv + k] = acc[b];
    }
    if (blockIdx.x == 0 && tid == 0) {
        const float rr = (float)nreads * (1.f / (float)Ll);
        for (int i = Bb * Vv; i < out_size; i++) out[i] = rr;
    }
}

extern "C" void kernel_launch(void* const* d_in, const int* in_sizes, int n_in,
                              void* d_out, int out_size) {
    const int*   seq    = (const int*)  d_in[0];
    const float* memory = (const float*)d_in[1];
    const float* embed  = (const float*)d_in[2];
    const float* gwih   = (const float*)d_in[3];
    const float* gwhh   = (const float*)d_in[4];
    const float* gbih   = (const float*)d_in[5];
    const float* gbhh   = (const float*)d_in[6];
    const float* qw     = (const float*)d_in[7];
    const float* qb     = (const float*)d_in[8];
    const float* kw     = (const float*)d_in[9];
    /* k_b (d_in[10]) cancels in softmax — unused */
    const float* vw     = (const float*)d_in[11];
    const float* vb     = (const float*)d_in[12];
    const float* lwih   = (const float*)d_in[13];
    const float* lwhh   = (const float*)d_in[14];
    const float* lbih   = (const float*)d_in[15];
    const float* lbhh   = (const float*)d_in[16];
    const float* trigw  = (const float*)d_in[17];
    const float* trigb  = (const float*)d_in[18];
    const float* headw  = (const float*)d_in[19];
    const float* headb  = (const float*)d_in[20];
    float* out = (float*)d_out;

    cudaFuncSetAttribute(model_kernel,
                         cudaFuncAttributeMaxDynamicSharedMemorySize, SMEM_BYTES);

    prep_kernel<<<64, 256>>>(embed, gwih, gbih, kw, qw, qb);
    model_kernel<<<NBLK, NT, SMEM_BYTES>>>(seq, memory, gwih, gwhh, gbhh,
                                           vw, vb, lwih, lwhh, lbih, lbhh,
                                           trigw, trigb, headw, headb,
                                           out, out_size);
}

// round 13
// speedup vs baseline: 1.5318x; 1.1671x over previous
#include <cuda_runtime.h>
#include <math.h>

#define Bb   1024
#define Ll   256
#define Mm   256
#define Hh   64
#define Vv   64
#define NB   8      // batches per block
#define NBLK 128
#define NT   256

// ---------------- device scratch ----------------
__device__ float d_E2[Vv * 192];       // embed @ Wx^T + b_ih   (64 x 192)
__device__ float d_A2[Hh * Hh];        // (q_w^T k_w) / 8  stored [a][l]
__device__ float d_a0[Hh];             // (q_b^T k_w) / 8
__device__ float d_gpart[Ll * NBLK];   // per-step per-block partial sums (+1.0 sentinel)

__device__ __forceinline__ float sigf(float x)     { return 1.f / (1.f + __expf(-x)); }
__device__ __forceinline__ float tanhfast(float x) { return 2.f / (1.f + __expf(-2.f * x)) - 1.f; }

__device__ __forceinline__ unsigned long long pack2(float a, float b) {
    unsigned long long r;
    asm("mov.b64 %0, {%1, %2};" : "=l"(r) : "f"(a), "f"(b));
    return r;
}
__device__ __forceinline__ void unpack2(unsigned long long v, float& a, float& b) {
    asm("mov.b64 {%0, %1}, %2;" : "=f"(a), "=f"(b) : "l"(v));
}
__device__ __forceinline__ void fma2(unsigned long long& d, unsigned long long a, unsigned long long b) {
    asm("fma.rn.f32x2 %0, %1, %2, %0;" : "+l"(d) : "l"(a), "l"(b));
}

// ---------------- prep ----------------
__global__ void prep_kernel(const float* __restrict__ embed,
                            const float* __restrict__ gwih,
                            const float* __restrict__ gbih,
                            const float* __restrict__ kw,
                            const float* __restrict__ qw,
                            const float* __restrict__ qb) {
    const int idx = blockIdx.x * blockDim.x + threadIdx.x;
    const int stride = gridDim.x * blockDim.x;
    for (int i = idx; i < Vv * 192; i += stride) {
        const int v = i / 192, k = i % 192;
        float s = gbih[k];
        const float* e = embed + v * Hh;
        const float* w = gwih + k * (2 * Hh);
        #pragma unroll 8
        for (int j = 0; j < Hh; j++) s = fmaf(e[j], w[j], s);
        d_E2[i] = s;
    }
    for (int i = idx; i < Hh * Hh; i += stride) {
        const int a = i >> 6, l = i & 63;
        float s = 0.f;
        for (int t = 0; t < Hh; t++) s = fmaf(kw[t * Hh + a], qw[t * Hh + l], s);
        d_A2[i] = s * 0.125f;
    }
    for (int i = idx; i < Hh; i += stride) {
        float s = 0.f;
        for (int t = 0; t < Hh; t++) s = fmaf(kw[t * Hh + i], qb[t], s);
        d_a0[i] = s * 0.125f;
    }
    for (int i = idx; i < Ll * NBLK; i += stride) d_gpart[i] = 0.f;
}

// ---------------- SMEM layout (float offsets) ----------------
#define OFF_GWHH 0        /* gwhh [k<192][j<64] pad 68 = 13056 (row-major, j-contig) */
#define OFF_E2   13056    /* full E2 table [v<64][k<192] = 12288 */
#define OFF_LWIH 25344    /* lwih [k<128][j<64] pad 68 = 8704 (row-major, j-contig) */
#define OFF_LWHH 34048    /* [j<32][u<32][g<4] = 4096 */
#define OFF_A2   38144    /* A2^T [l][a] = 4096 */
#define OFF_VW   42240    /* vw^T [j][k] = 4096 */
#define OFF_GBHH 46336    /* 192 */
#define OFF_LB2  46528    /* 128 lbih+lbhh */
#define OFF_A0   46656    /* 64 */
#define OFF_VB   46720    /* 64 */
#define OFF_TW   46784    /* 32 */
#define OFF_SC   46816    /* 4 */
#define OFF_HP   46820    /* 8x64 h state (16B-aligned) */
#define OFF_XW   47332    /* ring 4 x 8 x 128 (bias folded) */
#define OFF_GH   51428    /* 8 x 192 */
#define OFF_GI   52964    /* 8 x 192 */
#define OFF_Q2   54500    /* 8x64 */
#define OFF_WS   55012    /* 8x64 */
#define OFF_RET  55524    /* 8x64 */
#define OFF_PROB 56036    /* 8 */
#define OFF_RED  56044    /* 128 */
#define OFF_TOK  56172    /* 2 x 8 ints */
#define SMEM_FLOATS 56188
#define SMEM_BYTES  (SMEM_FLOATS * 4)

__global__ void __launch_bounds__(NT, 1) model_kernel(
    const int*   __restrict__ seq,
    const float* __restrict__ memory,
    const float* __restrict__ gwih,
    const float* __restrict__ gwhh,
    const float* __restrict__ gbhh,
    const float* __restrict__ vw,
    const float* __restrict__ vb,
    const float* __restrict__ lwih,
    const float* __restrict__ lwhh,
    const float* __restrict__ lbih,
    const float* __restrict__ lbhh,
    const float* __restrict__ trigw,
    const float* __restrict__ trigb,
    const float* __restrict__ headw,
    const float* __restrict__ headb,
    float* __restrict__ out,
    int out_size)
{
    extern __shared__ float sm[];
    const int tid = threadIdx.x;
    const int b0  = blockIdx.x * NB;
    int* s_tok = (int*)(sm + OFF_TOK);

    // ---- weight staging ----
    for (int i = tid; i < 192 * 64; i += NT) {           // gwhh row-major, pad 68
        const int k = i >> 6, j = i & 63;
        sm[OFF_GWHH + k * 68 + j] = gwhh[i];
    }
    for (int i = tid; i < 12288; i += NT)                // full E2 table
        sm[OFF_E2 + i] = d_E2[i];
    for (int i = tid; i < 128 * 64; i += NT) {           // lwih row-major, pad 68
        const int k = i >> 6, j = i & 63;
        sm[OFF_LWIH + k * 68 + j] = lwih[i];
    }
    for (int i = tid; i < 4096; i += NT) {               // lwhh [j][u][g]
        const int j = i >> 7, u = (i >> 2) & 31, g = i & 3;
        sm[OFF_LWHH + i] = lwhh[(g * 32 + u) * 32 + j];
    }
    for (int i = tid; i < 4096; i += NT)                 // A2^T [l][a]
        sm[OFF_A2 + i] = d_A2[(i % 64) * 64 + (i / 64)];
    for (int i = tid; i < 4096; i += NT)                 // vw^T [j][k]
        sm[OFF_VW + i] = vw[(i % 64) * 64 + (i / 64)];
    for (int i = tid; i < 192; i += NT) sm[OFF_GBHH + i] = gbhh[i];
    for (int i = tid; i < 128; i += NT) sm[OFF_LB2 + i] = lbih[i] + lbhh[i];
    for (int i = tid; i < 64; i += NT)  { sm[OFF_A0 + i] = d_a0[i]; sm[OFF_VB + i] = vb[i]; }
    for (int i = tid; i < 32; i += NT)  sm[OFF_TW + i] = trigw[i];
    if (tid == 0) sm[OFF_SC] = trigb[0];
    for (int i = tid; i < NB * Hh; i += NT) sm[OFF_HP + i] = 0.f;
    for (int i = tid; i < 1536; i += NT) sm[OFF_GH + i] = gbhh[i % 192];   // gh for t=0 (h=0)
    if (tid < NB) s_tok[tid] = seq[(b0 + tid) * Ll + 0];                    // tokens t=0 -> slot 0
    __syncthreads();

    int read_prev = 0;
    int nreads = 0;

    for (int t = 0; t < Ll; t++) {
        // ===== B: GRU combine -> new h (gh precomputed last step) =====
        #pragma unroll
        for (int it = tid; it < NB * Hh; it += NT) {
            const int b = it >> 6, k = it & 63;
            const int tok = s_tok[(t & 1) * 8 + b];
            float gi_r = sm[OFF_E2 + tok * 192 + k];
            float gi_z = sm[OFF_E2 + tok * 192 + 64 + k];
            float gi_n = sm[OFF_E2 + tok * 192 + 128 + k];
            if (read_prev) {
                gi_r += sm[OFF_GI + b * 192 + k];
                gi_z += sm[OFF_GI + b * 192 + 64 + k];
                gi_n += sm[OFF_GI + b * 192 + 128 + k];
            }
            const float gh_r = sm[OFF_GH + b * 192 + k];
            const float gh_z = sm[OFF_GH + b * 192 + 64 + k];
            const float gh_n = sm[OFF_GH + b * 192 + 128 + k];
            const float r = sigf(gi_r + gh_r);
            const float z = sigf(gi_z + gh_z);
            const float n = tanhfast(fmaf(r, gh_n, gi_n));
            const float h = sm[OFF_HP + b * 64 + k];
            sm[OFF_HP + b * 64 + k] = n + z * (h - n);   // (1-z)n + z h
        }
        __syncthreads();   // s1

        // ===== C: xW_t -> ring slot (threads 0-127, f32x2 j-paired) || token prefetch =====
        if (tid < 128) {
            const int k = tid;
            const ulonglong2* wrow = (const ulonglong2*)&sm[OFF_LWIH + k * 68];
            unsigned long long acc[NB];
            {
                const unsigned long long binit = pack2(sm[OFF_LB2 + k], 0.f);
                #pragma unroll
                for (int b = 0; b < NB; b++) acc[b] = binit;
            }
            #pragma unroll 4
            for (int g = 0; g < 16; g++) {
                const ulonglong2 w2 = wrow[g];
                #pragma unroll
                for (int b = 0; b < NB; b++) {
                    const ulonglong2 h2 = *(const ulonglong2*)&sm[OFF_HP + b * 64 + g * 4];
                    fma2(acc[b], w2.x, h2.x);
                    fma2(acc[b], w2.y, h2.y);
                }
            }
            float* xw = &sm[OFF_XW + (t & 3) * 1024];
            #pragma unroll
            for (int b = 0; b < NB; b++) {
                float lo, hi;
                unpack2(acc[b], lo, hi);
                xw[b * 128 + k] = lo + hi;
            }
        } else if (tid >= 248 && t + 1 < Ll) {
            s_tok[((t + 1) & 1) * 8 + (tid - 248)] = seq[(b0 + tid - 248) * Ll + (t + 1)];
        }
        __syncthreads();   // s2

        // ===== D: register LSTM trigger (warps 0-7, one batch each) =====
        if (t >= 3) {
            const int w = tid >> 5, u = tid & 31;
            float hh = 0.f, cc = 0.f;
            #pragma unroll
            for (int s = 0; s < 4; s++) {
                const int slot = (t + 1 + s) & 3;
                const float* xw = &sm[OFF_XW + slot * 1024 + w * 128];
                float gI = xw[u], gF = xw[32 + u], gG = xw[64 + u], gO = xw[96 + u];
                if (s > 0) {
                    #pragma unroll
                    for (int j = 0; j < 32; j++) {
                        const float hj = __shfl_sync(0xffffffffu, hh, j);
                        const float4 wv = *(const float4*)&sm[OFF_LWHH + (j * 32 + u) * 4];
                        gI = fmaf(wv.x, hj, gI); gF = fmaf(wv.y, hj, gF);
                        gG = fmaf(wv.z, hj, gG); gO = fmaf(wv.w, hj, gO);
                    }
                }
                float c = sigf(gI) * tanhfast(gG);
                if (s > 0) c = fmaf(sigf(gF), cc, c);
                cc = c;
                hh = sigf(gO) * tanhfast(c);
            }
            float v = hh * sm[OFF_TW + u];
            #pragma unroll
            for (int o = 16; o > 0; o >>= 1) v += __shfl_xor_sync(0xffffffffu, v, o);
            if (u == 0) sm[OFF_PROB + w] = sigf(v + sm[OFF_SC]);
        }
        __syncthreads();   // s3

        // ===== E: gh_{t+1} (threads 0-191, f32x2 j-paired) || post+poll (192-255) =====
        if (tid < 192) {
            const int k = tid;
            const ulonglong2* wrow = (const ulonglong2*)&sm[OFF_GWHH + k * 68];
            unsigned long long acc[NB];
            {
                const unsigned long long binit = pack2(sm[OFF_GBHH + k], 0.f);
                #pragma unroll
                for (int b = 0; b < NB; b++) acc[b] = binit;
            }
            #pragma unroll 4
            for (int g = 0; g < 16; g++) {
                const ulonglong2 w2 = wrow[g];
                #pragma unroll
                for (int b = 0; b < NB; b++) {
                    const ulonglong2 h2 = *(const ulonglong2*)&sm[OFF_HP + b * 64 + g * 4];
                    fma2(acc[b], w2.x, h2.x);
                    fma2(acc[b], w2.y, h2.y);
                }
            }
            #pragma unroll
            for (int b = 0; b < NB; b++) {
                float lo, hi;
                unpack2(acc[b], lo, hi);
                sm[OFF_GH + b * 192 + k] = lo + hi;
            }
        } else if (t >= 3) {
            const int i = tid - 192;                      // 64 pollers, 2 slots each
            if (i == 0) {                                 // poster
                float pv = sm[OFF_PROB + 0] + sm[OFF_PROB + 1] + sm[OFF_PROB + 2] + sm[OFF_PROB + 3]
                         + sm[OFF_PROB + 4] + sm[OFF_PROB + 5] + sm[OFF_PROB + 6] + sm[OFF_PROB + 7];
                asm volatile("st.global.cg.f32 [%0], %1;"
                             :: "l"(&d_gpart[t * NBLK + blockIdx.x]), "f"(pv + 1.f)
                             : "memory");
            }
            const float* g0 = &d_gpart[t * NBLK + i];
            const float* g1 = &d_gpart[t * NBLK + 64 + i];
            float v0, v1;
            do {
                asm volatile("ld.global.cg.f32 %0, [%1];" : "=f"(v0) : "l"(g0) : "memory");
            } while (v0 == 0.f);
            do {
                asm volatile("ld.global.cg.f32 %0, [%1];" : "=f"(v1) : "l"(g1) : "memory");
            } while (v1 == 0.f);
            sm[OFF_RED + i]      = v0 - 1.f;
            sm[OFF_RED + 64 + i] = v1 - 1.f;
        }
        __syncthreads();   // s4

        if (t >= 3) {
            // every warp reduces redundantly -> uniform do_read in registers
            const int ln = tid & 31;
            float s = sm[OFF_RED + ln] + sm[OFF_RED + 32 + ln]
                    + sm[OFF_RED + 64 + ln] + sm[OFF_RED + 96 + ln];
            #pragma unroll
            for (int o = 16; o > 0; o >>= 1) s += __shfl_xor_sync(0xffffffffu, s, o);
            const int do_read = (s > 512.f);

            if (do_read) {
                // ---- attention: q2 = A2 h + a0 ----
                if (tid < 64) {
                    const int k = tid;
                    float acc[NB];
                    #pragma unroll
                    for (int b = 0; b < NB; b++) acc[b] = sm[OFF_A0 + k];
                    #pragma unroll 4
                    for (int j = 0; j < 64; j += 4) {
                        const float w0 = sm[OFF_A2 + (j + 0) * 64 + k];
                        const float w1 = sm[OFF_A2 + (j + 1) * 64 + k];
                        const float w2 = sm[OFF_A2 + (j + 2) * 64 + k];
                        const float w3 = sm[OFF_A2 + (j + 3) * 64 + k];
                        #pragma unroll
                        for (int b = 0; b < NB; b++) {
                            const float4 h4 = *(const float4*)&sm[OFF_HP + b * 64 + j];
                            acc[b] = fmaf(w0, h4.x, acc[b]);
                            acc[b] = fmaf(w1, h4.y, acc[b]);
                            acc[b] = fmaf(w2, h4.z, acc[b]);
                            acc[b] = fmaf(w3, h4.w, acc[b]);
                        }
                    }
                    #pragma unroll
                    for (int b = 0; b < NB; b++) sm[OFF_Q2 + b * 64 + k] = acc[b];
                }
                __syncthreads();
                {   // streaming online softmax over memory (warp per batch)
                    const int w2 = tid >> 5, l2 = tid & 31;
                    const float* mb = memory + (size_t)(b0 + w2) * (Mm * Hh);
                    const float q0 = sm[OFF_Q2 + w2 * 64 + 2 * l2];
                    const float q1 = sm[OFF_Q2 + w2 * 64 + 2 * l2 + 1];
                    float mx = -3.0e38f, dn = 0.f, ra = 0.f, rb = 0.f;
                    #pragma unroll 4
                    for (int m = 0; m < Mm; m++) {
                        const float2 mmv = *(const float2*)(mb + m * 64 + 2 * l2);
                        float p = q0 * mmv.x + q1 * mmv.y;
                        #pragma unroll
                        for (int o = 16; o > 0; o >>= 1) p += __shfl_xor_sync(0xffffffffu, p, o);
                        const float nm = fmaxf(mx, p);
                        const float f  = __expf(mx - nm);
                        const float e  = __expf(p - nm);
                        dn = fmaf(dn, f, e);
                        ra = fmaf(ra, f, e * mmv.x);
                        rb = fmaf(rb, f, e * mmv.y);
                        mx = nm;
                    }
                    const float inv = 1.f / dn;
                    sm[OFF_WS + w2 * 64 + 2 * l2]     = ra * inv;
                    sm[OFF_WS + w2 * 64 + 2 * l2 + 1] = rb * inv;
                }
                __syncthreads();
                if (tid < 64) {   // retrieved = v_w ws + v_b
                    const int k = tid;
                    float acc[NB];
                    #pragma unroll
                    for (int b = 0; b < NB; b++) acc[b] = sm[OFF_VB + k];
                    #pragma unroll 4
                    for (int j = 0; j < 64; j += 4) {
                        const float w0 = sm[OFF_VW + (j + 0) * 64 + k];
                        const float w1 = sm[OFF_VW + (j + 1) * 64 + k];
                        const float w2 = sm[OFF_VW + (j + 2) * 64 + k];
                        const float w3 = sm[OFF_VW + (j + 3) * 64 + k];
                        #pragma unroll
                        for (int b = 0; b < NB; b++) {
                            const float4 s4 = *(const float4*)&sm[OFF_WS + b * 64 + j];
                            acc[b] = fmaf(w0, s4.x, acc[b]);
                            acc[b] = fmaf(w1, s4.y, acc[b]);
                            acc[b] = fmaf(w2, s4.z, acc[b]);
                            acc[b] = fmaf(w3, s4.w, acc[b]);
                        }
                    }
                    #pragma unroll
                    for (int b = 0; b < NB; b++) sm[OFF_RET + b * 64 + k] = acc[b];
                }
                __syncthreads();
                // GI = Wr . retrieved  (Wr read from global — rare path)
                if (tid < 192) {
                    const int k = tid;
                    float acc[NB];
                    #pragma unroll
                    for (int b = 0; b < NB; b++) acc[b] = 0.f;
                    const float* wr = &gwih[k * 128 + 64];
                    #pragma unroll 4
                    for (int j = 0; j < 64; j += 4) {
                        const float4 w4 = __ldg((const float4*)(wr + j));
                        #pragma unroll
                        for (int b = 0; b < NB; b++) {
                            const float4 r4 = *(const float4*)&sm[OFF_RET + b * 64 + j];
                            acc[b] = fmaf(w4.x, r4.x, acc[b]);
                            acc[b] = fmaf(w4.y, r4.y, acc[b]);
                            acc[b] = fmaf(w4.z, r4.z, acc[b]);
                            acc[b] = fmaf(w4.w, r4.w, acc[b]);
                        }
                    }
                    #pragma unroll
                    for (int b = 0; b < NB; b++) sm[OFF_GI + b * 192 + k] = acc[b];
                }
                __syncthreads();   // protect GI before next-step B
                nreads++;
            }
            read_prev = do_read;
        } else {
            read_prev = 0;
        }
        // next-step B (writes HP) is safe: gh readers of HP finished before s4
    }

    __syncthreads();
    // ---------- epilogue: logits = h @ head_w^T + head_b ----------
    if (tid < 64) {
        const int k = tid;
        float acc[NB];
        const float hb = __ldg(&headb[k]);
        #pragma unroll
        for (int b = 0; b < NB; b++) acc[b] = hb;
        #pragma unroll 4
        for (int j = 0; j < 64; j += 4) {
            const float4 w4 = __ldg((const float4*)(headw + k * 64 + j));
            #pragma unroll
            for (int b = 0; b < NB; b++) {
                const float4 h4 = *(const float4*)&sm[OFF_HP + b * 64 + j];
                acc[b] = fmaf(w4.x, h4.x, acc[b]);
                acc[b] = fmaf(w4.y, h4.y, acc[b]);
                acc[b] = fmaf(w4.z, h4.z, acc[b]);
                acc[b] = fmaf(w4.w, h4.w, acc[b]);
            }
        }
        #pragma unroll
        for (int b = 0; b < NB; b++) out[(size_t)(b0 + b) * Vv + k] = acc[b];
    }
    if (blockIdx.x == 0 && tid == 0) {
        const float rr = (float)nreads * (1.f / (float)Ll);
        for (int i = Bb * Vv; i < out_size; i++) out[i] = rr;
    }
}

extern "C" void kernel_launch(void* const* d_in, const int* in_sizes, int n_in,
                              void* d_out, int out_size) {
    const int*   seq    = (const int*)  d_in[0];
    const float* memory = (const float*)d_in[1];
    const float* embed  = (const float*)d_in[2];
    const float* gwih   = (const float*)d_in[3];
    const float* gwhh   = (const float*)d_in[4];
    const float* gbih   = (const float*)d_in[5];
    const float* gbhh   = (const float*)d_in[6];
    const float* qw     = (const float*)d_in[7];
    const float* qb     = (const float*)d_in[8];
    const float* kw     = (const float*)d_in[9];
    /* k_b (d_in[10]) cancels in softmax — unused */
    const float* vw     = (const float*)d_in[11];
    const float* vb     = (const float*)d_in[12];
    const float* lwih   = (const float*)d_in[13];
    const float* lwhh   = (const float*)d_in[14];
    const float* lbih   = (const float*)d_in[15];
    const float* lbhh   = (const float*)d_in[16];
    const float* trigw  = (const float*)d_in[17];
    const float* trigb  = (const float*)d_in[18];
    const float* headw  = (const float*)d_in[19];
    const float* headb  = (const float*)d_in[20];
    float* out = (float*)d_out;

    cudaFuncSetAttribute(model_kernel,
                         cudaFuncAttributeMaxDynamicSharedMemorySize, SMEM_BYTES);

    prep_kernel<<<64, 256>>>(embed, gwih, gbih, kw, qw, qb);
    model_kernel<<<NBLK, NT, SMEM_BYTES>>>(seq, memory, gwih, gwhh, gbhh,
                                           vw, vb, lwih, lwhh, lbih, lbhh,
                                           trigw, trigb, headw, headb,
                                           out, out_size);
}

// round 15
// speedup vs baseline: 1.5918x; 1.0392x over previous
#include <cuda_runtime.h>
#include <math.h>

#define Bb   1024
#define Ll   256
#define Mm   256
#define Hh   64
#define Vv   64
#define NB   8      // batches per block
#define NBLK 128
#define NT   256

// ---------------- device scratch ----------------
__device__ float d_E2[Vv * 192];       // embed @ Wx^T + b_ih   (64 x 192)
__device__ float d_A2[Hh * Hh];        // (q_w^T k_w) / 8  stored [a][l]
__device__ float d_a0[Hh];             // (q_b^T k_w) / 8
__device__ float d_gpart[Ll * NBLK];   // per-step per-block partial sums (+1.0 sentinel)

__device__ __forceinline__ float sigf(float x)     { return 1.f / (1.f + __expf(-x)); }
__device__ __forceinline__ float tanhfast(float x) { return 2.f / (1.f + __expf(-2.f * x)) - 1.f; }

__device__ __forceinline__ unsigned long long pack2(float a, float b) {
    unsigned long long r;
    asm("mov.b64 %0, {%1, %2};" : "=l"(r) : "f"(a), "f"(b));
    return r;
}
__device__ __forceinline__ void unpack2(unsigned long long v, float& a, float& b) {
    asm("mov.b64 {%0, %1}, %2;" : "=f"(a), "=f"(b) : "l"(v));
}
__device__ __forceinline__ void fma2(unsigned long long& d, unsigned long long a, unsigned long long b) {
    asm("fma.rn.f32x2 %0, %1, %2, %0;" : "+l"(d) : "l"(a), "l"(b));
}

// round-to-nearest-even bf16, returned as f32 bit-pattern (high 16 bits kept)
__device__ __forceinline__ unsigned int bfr(float x) {
    unsigned int b = __float_as_uint(x);
    return (b + 0x7fffu + ((b >> 16) & 1u)) & 0xffff0000u;
}

// ---------------- prep ----------------
__global__ void prep_kernel(const float* __restrict__ embed,
                            const float* __restrict__ gwih,
                            const float* __restrict__ gbih,
                            const float* __restrict__ kw,
                            const float* __restrict__ qw,
                            const float* __restrict__ qb) {
    const int idx = blockIdx.x * blockDim.x + threadIdx.x;
    const int stride = gridDim.x * blockDim.x;
    for (int i = idx; i < Vv * 192; i += stride) {
        const int v = i / 192, k = i % 192;
        float s = gbih[k];
        const float* e = embed + v * Hh;
        const float* w = gwih + k * (2 * Hh);
        #pragma unroll 8
        for (int j = 0; j < Hh; j++) s = fmaf(e[j], w[j], s);
        d_E2[i] = s;
    }
    for (int i = idx; i < Hh * Hh; i += stride) {
        const int a = i >> 6, l = i & 63;
        float s = 0.f;
        for (int t = 0; t < Hh; t++) s = fmaf(kw[t * Hh + a], qw[t * Hh + l], s);
        d_A2[i] = s * 0.125f;
    }
    for (int i = idx; i < Hh; i += stride) {
        float s = 0.f;
        for (int t = 0; t < Hh; t++) s = fmaf(kw[t * Hh + i], qb[t], s);
        d_a0[i] = s * 0.125f;
    }
    for (int i = idx; i < Ll * NBLK; i += stride) d_gpart[i] = 0.f;
}

// ---------------- SMEM layout (float offsets) ----------------
#define OFF_GWHH  0       /* gwhh [k<192][j<64] pad 68 = 13056 (row-major, j-contig) */
#define OFF_E2    13056   /* full E2 table [v<64][k<192] = 12288 */
#define OFF_LWIH  25344   /* lwih [k<128][j<64] pad 68 = 8704 (row-major, j-contig) */
#define OFF_LWHHB 34048   /* lwhh bf16x2 [j<32][u<32][2] = 2048 uint32 (8KB) */
#define OFF_A2    36096   /* A2^T [l][a] = 4096 */
#define OFF_VW    40192   /* vw^T [j][k] = 4096 */
#define OFF_GBHH  44288   /* 192 */
#define OFF_LB2   44480   /* 128 lbih+lbhh */
#define OFF_A0    44608   /* 64 */
#define OFF_VB    44672   /* 64 */
#define OFF_TW    44736   /* 32 */
#define OFF_SC    44768   /* 4 */
#define OFF_HP    44772   /* 8x64 h state (16B-aligned) */
#define OFF_XW    45284   /* ring 4 x 8 x 128 (bias folded) */
#define OFF_GH    49380   /* 8 x 192 */
#define OFF_GI    50916   /* 8 x 192 */
#define OFF_Q2    52452   /* 8x64 */
#define OFF_WS    52964   /* 8x64 */
#define OFF_RET   53476   /* 8x64 */
#define OFF_PROB  53988   /* 8 */
#define OFF_RED   53996   /* 128 */
#define OFF_TOK   54124   /* 2 x 8 ints */
#define SMEM_FLOATS 54140
#define SMEM_BYTES  (SMEM_FLOATS * 4)

__global__ void __launch_bounds__(NT, 1) model_kernel(
    const int*   __restrict__ seq,
    const float* __restrict__ memory,
    const float* __restrict__ gwih,
    const float* __restrict__ gwhh,
    const float* __restrict__ gbhh,
    const float* __restrict__ vw,
    const float* __restrict__ vb,
    const float* __restrict__ lwih,
    const float* __restrict__ lwhh,
    const float* __restrict__ lbih,
    const float* __restrict__ lbhh,
    const float* __restrict__ trigw,
    const float* __restrict__ trigb,
    const float* __restrict__ headw,
    const float* __restrict__ headb,
    float* __restrict__ out,
    int out_size)
{
    extern __shared__ float sm[];
    const int tid = threadIdx.x;
    const int b0  = blockIdx.x * NB;
    int* s_tok = (int*)(sm + OFF_TOK);
    unsigned int* smB = (unsigned int*)(sm + OFF_LWHHB);

    // ---- weight staging ----
    for (int i = tid; i < 192 * 64; i += NT) {           // gwhh row-major, pad 68
        const int k = i >> 6, j = i & 63;
        sm[OFF_GWHH + k * 68 + j] = gwhh[i];
    }
    for (int i = tid; i < 12288; i += NT)                // full E2 table
        sm[OFF_E2 + i] = d_E2[i];
    for (int i = tid; i < 128 * 64; i += NT) {           // lwih row-major, pad 68
        const int k = i >> 6, j = i & 63;
        sm[OFF_LWIH + k * 68 + j] = lwih[i];
    }
    for (int i = tid; i < 2048; i += NT) {               // lwhh -> bf16 pairs [j][u][p]
        const int j = i >> 6, u = (i >> 1) & 31, p = i & 1;
        const float w0 = lwhh[((2 * p + 0) * 32 + u) * 32 + j];
        const float w1 = lwhh[((2 * p + 1) * 32 + u) * 32 + j];
        smB[i] = (bfr(w0) >> 16) | bfr(w1);
    }
    for (int i = tid; i < 4096; i += NT)                 // A2^T [l][a]
        sm[OFF_A2 + i] = d_A2[(i % 64) * 64 + (i / 64)];
    for (int i = tid; i < 4096; i += NT)                 // vw^T [j][k]
        sm[OFF_VW + i] = vw[(i % 64) * 64 + (i / 64)];
    for (int i = tid; i < 192; i += NT) sm[OFF_GBHH + i] = gbhh[i];
    for (int i = tid; i < 128; i += NT) sm[OFF_LB2 + i] = lbih[i] + lbhh[i];
    for (int i = tid; i < 64; i += NT)  { sm[OFF_A0 + i] = d_a0[i]; sm[OFF_VB + i] = vb[i]; }
    for (int i = tid; i < 32; i += NT)  sm[OFF_TW + i] = trigw[i];
    if (tid == 0) sm[OFF_SC] = trigb[0];
    for (int i = tid; i < NB * Hh; i += NT) sm[OFF_HP + i] = 0.f;
    for (int i = tid; i < 1536; i += NT) sm[OFF_GH + i] = gbhh[i % 192];   // gh for t=0 (h=0)
    if (tid < NB) s_tok[tid] = seq[(b0 + tid) * Ll + 0];                    // tokens t=0 -> slot 0
    __syncthreads();

    int read_prev = 0;
    int nreads = 0;

    for (int t = 0; t < Ll; t++) {
        // ===== B: GRU combine -> new h (gh precomputed last step) =====
        #pragma unroll
        for (int it = tid; it < NB * Hh; it += NT) {
            const int b = it >> 6, k = it & 63;
            const int tok = s_tok[(t & 1) * 8 + b];
            float gi_r = sm[OFF_E2 + tok * 192 + k];
            float gi_z = sm[OFF_E2 + tok * 192 + 64 + k];
            float gi_n = sm[OFF_E2 + tok * 192 + 128 + k];
            if (read_prev) {
                gi_r += sm[OFF_GI + b * 192 + k];
                gi_z += sm[OFF_GI + b * 192 + 64 + k];
                gi_n += sm[OFF_GI + b * 192 + 128 + k];
            }
            const float gh_r = sm[OFF_GH + b * 192 + k];
            const float gh_z = sm[OFF_GH + b * 192 + 64 + k];
            const float gh_n = sm[OFF_GH + b * 192 + 128 + k];
            const float r = sigf(gi_r + gh_r);
            const float z = sigf(gi_z + gh_z);
            const float n = tanhfast(fmaf(r, gh_n, gi_n));
            const float h = sm[OFF_HP + b * 64 + k];
            sm[OFF_HP + b * 64 + k] = n + z * (h - n);   // (1-z)n + z h
        }
        __syncthreads();   // s1

        // ===== C: xW_t -> ring slot (threads 0-127, f32x2 j-paired) || token prefetch =====
        if (tid < 128) {
            const int k = tid;
            const ulonglong2* wrow = (const ulonglong2*)&sm[OFF_LWIH + k * 68];
            unsigned long long acc[NB];
            {
                const unsigned long long binit = pack2(sm[OFF_LB2 + k], 0.f);
                #pragma unroll
                for (int b = 0; b < NB; b++) acc[b] = binit;
            }
            #pragma unroll 4
            for (int g = 0; g < 16; g++) {
                const ulonglong2 w2 = wrow[g];
                #pragma unroll
                for (int b = 0; b < NB; b++) {
                    const ulonglong2 h2 = *(const ulonglong2*)&sm[OFF_HP + b * 64 + g * 4];
                    fma2(acc[b], w2.x, h2.x);
                    fma2(acc[b], w2.y, h2.y);
                }
            }
            float* xw = &sm[OFF_XW + (t & 3) * 1024];
            #pragma unroll
            for (int b = 0; b < NB; b++) {
                float lo, hi;
                unpack2(acc[b], lo, hi);
                xw[b * 128 + k] = lo + hi;
            }
        } else if (tid >= 248 && t + 1 < Ll) {
            s_tok[((t + 1) & 1) * 8 + (tid - 248)] = seq[(b0 + tid - 248) * Ll + (t + 1)];
        }
        __syncthreads();   // s2

        // ===== D: register LSTM trigger (warps 0-7, one batch each; bf16 weights) =====
        if (t >= 3) {
            const int w = tid >> 5, u = tid & 31;
            float hh = 0.f, cc = 0.f;
            #pragma unroll
            for (int s = 0; s < 4; s++) {
                const int slot = (t + 1 + s) & 3;
                const float* xw = &sm[OFF_XW + slot * 1024 + w * 128];
                float gI = xw[u], gF = xw[32 + u], gG = xw[64 + u], gO = xw[96 + u];
                if (s > 0) {
                    #pragma unroll
                    for (int j = 0; j < 32; j++) {
                        const float hj = __shfl_sync(0xffffffffu, hh, j);
                        const uint2 wp = *(const uint2*)&smB[(j * 32 + u) * 2];
                        gI = fmaf(__uint_as_float(wp.x << 16),         hj, gI);
                        gF = fmaf(__uint_as_float(wp.x & 0xffff0000u), hj, gF);
                        gG = fmaf(__uint_as_float(wp.y << 16),         hj, gG);
                        gO = fmaf(__uint_as_float(wp.y & 0xffff0000u), hj, gO);
                    }
                }
                float c = sigf(gI) * tanhfast(gG);
                if (s > 0) c = fmaf(sigf(gF), cc, c);
                cc = c;
                hh = sigf(gO) * tanhfast(c);
            }
            float v = hh * sm[OFF_TW + u];
            #pragma unroll
            for (int o = 16; o > 0; o >>= 1) v += __shfl_xor_sync(0xffffffffu, v, o);
            if (u == 0) sm[OFF_PROB + w] = sigf(v + sm[OFF_SC]);
        }
        __syncthreads();   // s3

        // ===== E: gh_{t+1} (threads 0-191, f32x2 j-paired) || post+poll (192-255) =====
        if (tid < 192) {
            const int k = tid;
            const ulonglong2* wrow = (const ulonglong2*)&sm[OFF_GWHH + k * 68];
            unsigned long long acc[NB];
            {
                const unsigned long long binit = pack2(sm[OFF_GBHH + k], 0.f);
                #pragma unroll
                for (int b = 0; b < NB; b++) acc[b] = binit;
            }
            #pragma unroll 4
            for (int g = 0; g < 16; g++) {
                const ulonglong2 w2 = wrow[g];
                #pragma unroll
                for (int b = 0; b < NB; b++) {
                    const ulonglong2 h2 = *(const ulonglong2*)&sm[OFF_HP + b * 64 + g * 4];
                    fma2(acc[b], w2.x, h2.x);
                    fma2(acc[b], w2.y, h2.y);
                }
            }
            #pragma unroll
            for (int b = 0; b < NB; b++) {
                float lo, hi;
                unpack2(acc[b], lo, hi);
                sm[OFF_GH + b * 192 + k] = lo + hi;
            }
        } else if (t >= 3) {
            const int i = tid - 192;                      // 64 pollers, 2 slots each
            if (i == 0) {                                 // poster
                float pv = sm[OFF_PROB + 0] + sm[OFF_PROB + 1] + sm[OFF_PROB + 2] + sm[OFF_PROB + 3]
                         + sm[OFF_PROB + 4] + sm[OFF_PROB + 5] + sm[OFF_PROB + 6] + sm[OFF_PROB + 7];
                asm volatile("st.global.cg.f32 [%0], %1;"
                             :: "l"(&d_gpart[t * NBLK + blockIdx.x]), "f"(pv + 1.f)
                             : "memory");
            }
            const float* g0 = &d_gpart[t * NBLK + i];
            const float* g1 = &d_gpart[t * NBLK + 64 + i];
            float v0, v1;
            do {
                asm volatile("ld.global.cg.f32 %0, [%1];" : "=f"(v0) : "l"(g0) : "memory");
            } while (v0 == 0.f);
            do {
                asm volatile("ld.global.cg.f32 %0, [%1];" : "=f"(v1) : "l"(g1) : "memory");
            } while (v1 == 0.f);
            sm[OFF_RED + i]      = v0 - 1.f;
            sm[OFF_RED + 64 + i] = v1 - 1.f;
        }
        __syncthreads();   // s4

        if (t >= 3) {
            // every warp reduces redundantly -> uniform do_read in registers
            const int ln = tid & 31;
            float s = sm[OFF_RED + ln] + sm[OFF_RED + 32 + ln]
                    + sm[OFF_RED + 64 + ln] + sm[OFF_RED + 96 + ln];
            #pragma unroll
            for (int o = 16; o > 0; o >>= 1) s += __shfl_xor_sync(0xffffffffu, s, o);
            const int do_read = (s > 512.f);

            if (do_read) {
                // ---- attention: q2 = A2 h + a0 ----
                if (tid < 64) {
                    const int k = tid;
                    float acc[NB];
                    #pragma unroll
                    for (int b = 0; b < NB; b++) acc[b] = sm[OFF_A0 + k];
                    #pragma unroll 4
                    for (int j = 0; j < 64; j += 4) {
                        const float w0 = sm[OFF_A2 + (j + 0) * 64 + k];
                        const float w1 = sm[OFF_A2 + (j + 1) * 64 + k];
                        const float w2 = sm[OFF_A2 + (j + 2) * 64 + k];
                        const float w3 = sm[OFF_A2 + (j + 3) * 64 + k];
                        #pragma unroll
                        for (int b = 0; b < NB; b++) {
                            const float4 h4 = *(const float4*)&sm[OFF_HP + b * 64 + j];
                            acc[b] = fmaf(w0, h4.x, acc[b]);
                            acc[b] = fmaf(w1, h4.y, acc[b]);
                            acc[b] = fmaf(w2, h4.z, acc[b]);
                            acc[b] = fmaf(w3, h4.w, acc[b]);
                        }
                    }
                    #pragma unroll
                    for (int b = 0; b < NB; b++) sm[OFF_Q2 + b * 64 + k] = acc[b];
                }
                __syncthreads();
                {   // streaming online softmax over memory (warp per batch)
                    const int w2 = tid >> 5, l2 = tid & 31;
                    const float* mb = memory + (size_t)(b0 + w2) * (Mm * Hh);
                    const float q0 = sm[OFF_Q2 + w2 * 64 + 2 * l2];
                    const float q1 = sm[OFF_Q2 + w2 * 64 + 2 * l2 + 1];
                    float mx = -3.0e38f, dn = 0.f, ra = 0.f, rb = 0.f;
                    #pragma unroll 4
                    for (int m = 0; m < Mm; m++) {
                        const float2 mmv = *(const float2*)(mb + m * 64 + 2 * l2);
                        float p = q0 * mmv.x + q1 * mmv.y;
                        #pragma unroll
                        for (int o = 16; o > 0; o >>= 1) p += __shfl_xor_sync(0xffffffffu, p, o);
                        const float nm = fmaxf(mx, p);
                        const float f  = __expf(mx - nm);
                        const float e  = __expf(p - nm);
                        dn = fmaf(dn, f, e);
                        ra = fmaf(ra, f, e * mmv.x);
                        rb = fmaf(rb, f, e * mmv.y);
                        mx = nm;
                    }
                    const float inv = 1.f / dn;
                    sm[OFF_WS + w2 * 64 + 2 * l2]     = ra * inv;
                    sm[OFF_WS + w2 * 64 + 2 * l2 + 1] = rb * inv;
                }
                __syncthreads();
                if (tid < 64) {   // retrieved = v_w ws + v_b
                    const int k = tid;
                    float acc[NB];
                    #pragma unroll
                    for (int b = 0; b < NB; b++) acc[b] = sm[OFF_VB + k];
                    #pragma unroll 4
                    for (int j = 0; j < 64; j += 4) {
                        const float w0 = sm[OFF_VW + (j + 0) * 64 + k];
                        const float w1 = sm[OFF_VW + (j + 1) * 64 + k];
                        const float w2 = sm[OFF_VW + (j + 2) * 64 + k];
                        const float w3 = sm[OFF_VW + (j + 3) * 64 + k];
                        #pragma unroll
                        for (int b = 0; b < NB; b++) {
                            const float4 s4 = *(const float4*)&sm[OFF_WS + b * 64 + j];
                            acc[b] = fmaf(w0, s4.x, acc[b]);
                            acc[b] = fmaf(w1, s4.y, acc[b]);
                            acc[b] = fmaf(w2, s4.z, acc[b]);
                            acc[b] = fmaf(w3, s4.w, acc[b]);
                        }
                    }
                    #pragma unroll
                    for (int b = 0; b < NB; b++) sm[OFF_RET + b * 64 + k] = acc[b];
                }
                __syncthreads();
                // GI = Wr . retrieved  (Wr read from global — rare path)
                if (tid < 192) {
                    const int k = tid;
                    float acc[NB];
                    #pragma unroll
                    for (int b = 0; b < NB; b++) acc[b] = 0.f;
                    const float* wr = &gwih[k * 128 + 64];
                    #pragma unroll 4
                    for (int j = 0; j < 64; j += 4) {
                        const float4 w4 = __ldg((const float4*)(wr + j));
                        #pragma unroll
                        for (int b = 0; b < NB; b++) {
                            const float4 r4 = *(const float4*)&sm[OFF_RET + b * 64 + j];
                            acc[b] = fmaf(w4.x, r4.x, acc[b]);
                            acc[b] = fmaf(w4.y, r4.y, acc[b]);
                            acc[b] = fmaf(w4.z, r4.z, acc[b]);
                            acc[b] = fmaf(w4.w, r4.w, acc[b]);
                        }
                    }
                    #pragma unroll
                    for (int b = 0; b < NB; b++) sm[OFF_GI + b * 192 + k] = acc[b];
                }
                __syncthreads();   // protect GI before next-step B
                nreads++;
            }
            read_prev = do_read;
        } else {
            read_prev = 0;
        }
        // next-step B (writes HP) is safe: gh readers of HP finished before s4
    }

    __syncthreads();
    // ---------- epilogue: logits = h @ head_w^T + head_b ----------
    if (tid < 64) {
        const int k = tid;
        float acc[NB];
        const float hb = __ldg(&headb[k]);
        #pragma unroll
        for (int b = 0; b < NB; b++) acc[b] = hb;
        #pragma unroll 4
        for (int j = 0; j < 64; j += 4) {
            const float4 w4 = __ldg((const float4*)(headw + k * 64 + j));
            #pragma unroll
            for (int b = 0; b < NB; b++) {
                const float4 h4 = *(const float4*)&sm[OFF_HP + b * 64 + j];
                acc[b] = fmaf(w4.x, h4.x, acc[b]);
                acc[b] = fmaf(w4.y, h4.y, acc[b]);
                acc[b] = fmaf(w4.z, h4.z, acc[b]);
                acc[b] = fmaf(w4.w, h4.w, acc[b]);
            }
        }
        #pragma unroll
        for (int b = 0; b < NB; b++) out[(size_t)(b0 + b) * Vv + k] = acc[b];
    }
    if (blockIdx.x == 0 && tid == 0) {
        const float rr = (float)nreads * (1.f / (float)Ll);
        for (int i = Bb * Vv; i < out_size; i++) out[i] = rr;
    }
}

extern "C" void kernel_launch(void* const* d_in, const int* in_sizes, int n_in,
                              void* d_out, int out_size) {
    const int*   seq    = (const int*)  d_in[0];
    const float* memory = (const float*)d_in[1];
    const float* embed  = (const float*)d_in[2];
    const float* gwih   = (const float*)d_in[3];
    const float* gwhh   = (const float*)d_in[4];
    const float* gbih   = (const float*)d_in[5];
    const float* gbhh   = (const float*)d_in[6];
    const float* qw     = (const float*)d_in[7];
    const float* qb     = (const float*)d_in[8];
    const float* kw     = (const float*)d_in[9];
    /* k_b (d_in[10]) cancels in softmax — unused */
    const float* vw     = (const float*)d_in[11];
    const float* vb     = (const float*)d_in[12];
    const float* lwih   = (const float*)d_in[13];
    const float* lwhh   = (const float*)d_in[14];
    const float* lbih   = (const float*)d_in[15];
    const float* lbhh   = (const float*)d_in[16];
    const float* trigw  = (const float*)d_in[17];
    const float* trigb  = (const float*)d_in[18];
    const float* headw  = (const float*)d_in[19];
    const float* headb  = (const float*)d_in[20];
    float* out = (float*)d_out;

    cudaFuncSetAttribute(model_kernel,
                         cudaFuncAttributeMaxDynamicSharedMemorySize, SMEM_BYTES);

    prep_kernel<<<64, 256>>>(embed, gwih, gbih, kw, qw, qb);
    model_kernel<<<NBLK, NT, SMEM_BYTES>>>(seq, memory, gwih, gwhh, gbhh,
                                           vw, vb, lwih, lwhh, lbih, lbhh,
                                           trigw, trigb, headw, headb,
                                           out, out_size);
}

// round 16
// speedup vs baseline: 1.9719x; 1.2388x over previous
#include <cuda_runtime.h>
#include <math.h>

#define Bb   1024
#define Ll   256
#define Mm   256
#define Hh   64
#define Vv   64
#define NB   8      // batches per block
#define NBLK 128
#define NT   256

// ---------------- device scratch ----------------
__device__ float d_E2[Vv * 192];       // embed @ Wx^T + b_ih   (64 x 192)
__device__ float d_A2[Hh * Hh];        // (q_w^T k_w) / 8  stored [a][l]
__device__ float d_a0[Hh];             // (q_b^T k_w) / 8
__device__ float d_gpart[Ll * NBLK];   // per-step per-block partial sums (+1.0 sentinel)

__device__ __forceinline__ float sigf(float x)     { return 1.f / (1.f + __expf(-x)); }
__device__ __forceinline__ float tanhfast(float x) { return 2.f / (1.f + __expf(-2.f * x)) - 1.f; }

// HW tanh (MUFU.TANH) — trigger path only (decision tolerant, proven by bf16 win)
__device__ __forceinline__ float tanha(float x) {
    float r;
    asm("tanh.approx.f32 %0, %1;" : "=f"(r) : "f"(x));
    return r;
}
__device__ __forceinline__ float siga(float x) {
    return fmaf(tanha(0.5f * x), 0.5f, 0.5f);
}

__device__ __forceinline__ unsigned long long pack2(float a, float b) {
    unsigned long long r;
    asm("mov.b64 %0, {%1, %2};" : "=l"(r) : "f"(a), "f"(b));
    return r;
}
__device__ __forceinline__ void unpack2(unsigned long long v, float& a, float& b) {
    asm("mov.b64 {%0, %1}, %2;" : "=f"(a), "=f"(b) : "l"(v));
}
__device__ __forceinline__ void fma2(unsigned long long& d, unsigned long long a, unsigned long long b) {
    asm("fma.rn.f32x2 %0, %1, %2, %0;" : "+l"(d) : "l"(a), "l"(b));
}

// round-to-nearest-even bf16, returned as f32 bit-pattern (high 16 bits kept)
__device__ __forceinline__ unsigned int bfr(float x) {
    unsigned int b = __float_as_uint(x);
    return (b + 0x7fffu + ((b >> 16) & 1u)) & 0xffff0000u;
}

// ---------------- prep ----------------
__global__ void prep_kernel(const float* __restrict__ embed,
                            const float* __restrict__ gwih,
                            const float* __restrict__ gbih,
                            const float* __restrict__ kw,
                            const float* __restrict__ qw,
                            const float* __restrict__ qb) {
    const int idx = blockIdx.x * blockDim.x + threadIdx.x;
    const int stride = gridDim.x * blockDim.x;
    for (int i = idx; i < Vv * 192; i += stride) {
        const int v = i / 192, k = i % 192;
        float s = gbih[k];
        const float* e = embed + v * Hh;
        const float* w = gwih + k * (2 * Hh);
        #pragma unroll 8
        for (int j = 0; j < Hh; j++) s = fmaf(e[j], w[j], s);
        d_E2[i] = s;
    }
    for (int i = idx; i < Hh * Hh; i += stride) {
        const int a = i >> 6, l = i & 63;
        float s = 0.f;
        for (int t = 0; t < Hh; t++) s = fmaf(kw[t * Hh + a], qw[t * Hh + l], s);
        d_A2[i] = s * 0.125f;
    }
    for (int i = idx; i < Hh; i += stride) {
        float s = 0.f;
        for (int t = 0; t < Hh; t++) s = fmaf(kw[t * Hh + i], qb[t], s);
        d_a0[i] = s * 0.125f;
    }
    for (int i = idx; i < Ll * NBLK; i += stride) d_gpart[i] = 0.f;
}

// ---------------- SMEM layout (float offsets) ----------------
#define OFF_GWHH  0       /* gwhh [k<192][j<64] pad 68 = 13056 (row-major, j-contig) */
#define OFF_E2    13056   /* full E2 table [v<64][k<192] = 12288 */
#define OFF_LWIH  25344   /* lwih [k<128][j<64] pad 68 = 8704 (row-major, j-contig) */
#define OFF_LWHHB 34048   /* lwhh bf16x2 [j<32][u<32][2] = 2048 uint32 (8KB) */
#define OFF_A2    36096   /* A2^T [l][a] = 4096 */
#define OFF_VW    40192   /* vw^T [j][k] = 4096 */
#define OFF_GBHH  44288   /* 192 */
#define OFF_LB2   44480   /* 128 lbih+lbhh */
#define OFF_A0    44608   /* 64 */
#define OFF_VB    44672   /* 64 */
#define OFF_TW    44736   /* 32 */
#define OFF_SC    44768   /* 4 */
#define OFF_HP    44772   /* 8x64 h state (16B-aligned) */
#define OFF_XW    45284   /* ring 4 x 8 x 128 (bias folded) */
#define OFF_GH    49380   /* 8 x 192 */
#define OFF_GI    50916   /* 8 x 192 */
#define OFF_Q2    52452   /* 8x64 */
#define OFF_WS    52964   /* 8x64 */
#define OFF_RET   53476   /* 8x64 */
#define OFF_PROB  53988   /* 8 */
#define OFF_RED   53996   /* 128 */
#define OFF_TOK   54124   /* 2 x 8 ints */
#define SMEM_FLOATS 54140
#define SMEM_BYTES  (SMEM_FLOATS * 4)

__global__ void __launch_bounds__(NT, 1) model_kernel(
    const int*   __restrict__ seq,
    const float* __restrict__ memory,
    const float* __restrict__ gwih,
    const float* __restrict__ gwhh,
    const float* __restrict__ gbhh,
    const float* __restrict__ vw,
    const float* __restrict__ vb,
    const float* __restrict__ lwih,
    const float* __restrict__ lwhh,
    const float* __restrict__ lbih,
    const float* __restrict__ lbhh,
    const float* __restrict__ trigw,
    const float* __restrict__ trigb,
    const float* __restrict__ headw,
    const float* __restrict__ headb,
    float* __restrict__ out,
    int out_size)
{
    extern __shared__ float sm[];
    const int tid = threadIdx.x;
    const int b0  = blockIdx.x * NB;
    int* s_tok = (int*)(sm + OFF_TOK);
    unsigned int* smB = (unsigned int*)(sm + OFF_LWHHB);

    // ---- weight staging ----
    for (int i = tid; i < 192 * 64; i += NT) {           // gwhh row-major, pad 68
        const int k = i >> 6, j = i & 63;
        sm[OFF_GWHH + k * 68 + j] = gwhh[i];
    }
    for (int i = tid; i < 12288; i += NT)                // full E2 table
        sm[OFF_E2 + i] = d_E2[i];
    for (int i = tid; i < 128 * 64; i += NT) {           // lwih row-major, pad 68
        const int k = i >> 6, j = i & 63;
        sm[OFF_LWIH + k * 68 + j] = lwih[i];
    }
    for (int i = tid; i < 2048; i += NT) {               // lwhh -> bf16 pairs [j][u][p]
        const int j = i >> 6, u = (i >> 1) & 31, p = i & 1;
        const float w0 = lwhh[((2 * p + 0) * 32 + u) * 32 + j];
        const float w1 = lwhh[((2 * p + 1) * 32 + u) * 32 + j];
        smB[i] = (bfr(w0) >> 16) | bfr(w1);
    }
    for (int i = tid; i < 4096; i += NT)                 // A2^T [l][a]
        sm[OFF_A2 + i] = d_A2[(i % 64) * 64 + (i / 64)];
    for (int i = tid; i < 4096; i += NT)                 // vw^T [j][k]
        sm[OFF_VW + i] = vw[(i % 64) * 64 + (i / 64)];
    for (int i = tid; i < 192; i += NT) sm[OFF_GBHH + i] = gbhh[i];
    for (int i = tid; i < 128; i += NT) sm[OFF_LB2 + i] = lbih[i] + lbhh[i];
    for (int i = tid; i < 64; i += NT)  { sm[OFF_A0 + i] = d_a0[i]; sm[OFF_VB + i] = vb[i]; }
    for (int i = tid; i < 32; i += NT)  sm[OFF_TW + i] = trigw[i];
    if (tid == 0) sm[OFF_SC] = trigb[0];
    for (int i = tid; i < NB * Hh; i += NT) sm[OFF_HP + i] = 0.f;
    for (int i = tid; i < 1536; i += NT) sm[OFF_GH + i] = gbhh[i % 192];   // gh for t=0 (h=0)
    if (tid < NB) s_tok[tid] = seq[(b0 + tid) * Ll + 0];                    // tokens t=0 -> slot 0
    __syncthreads();

    int read_prev = 0;
    int nreads = 0;

    for (int t = 0; t < Ll; t++) {
        // ===== B: GRU combine -> new h (gh precomputed last step; exact nonlinearities) =====
        #pragma unroll
        for (int it = tid; it < NB * Hh; it += NT) {
            const int b = it >> 6, k = it & 63;
            const int tok = s_tok[(t & 1) * 8 + b];
            float gi_r = sm[OFF_E2 + tok * 192 + k];
            float gi_z = sm[OFF_E2 + tok * 192 + 64 + k];
            float gi_n = sm[OFF_E2 + tok * 192 + 128 + k];
            if (read_prev) {
                gi_r += sm[OFF_GI + b * 192 + k];
                gi_z += sm[OFF_GI + b * 192 + 64 + k];
                gi_n += sm[OFF_GI + b * 192 + 128 + k];
            }
            const float gh_r = sm[OFF_GH + b * 192 + k];
            const float gh_z = sm[OFF_GH + b * 192 + 64 + k];
            const float gh_n = sm[OFF_GH + b * 192 + 128 + k];
            const float r = sigf(gi_r + gh_r);
            const float z = sigf(gi_z + gh_z);
            const float n = tanhfast(fmaf(r, gh_n, gi_n));
            const float h = sm[OFF_HP + b * 64 + k];
            sm[OFF_HP + b * 64 + k] = n + z * (h - n);   // (1-z)n + z h
        }
        __syncthreads();   // s1

        // ===== C: xW_t -> ring slot (threads 0-127, f32x2 j-paired) || token prefetch =====
        if (tid < 128) {
            const int k = tid;
            const ulonglong2* wrow = (const ulonglong2*)&sm[OFF_LWIH + k * 68];
            unsigned long long acc[NB];
            {
                const unsigned long long binit = pack2(sm[OFF_LB2 + k], 0.f);
                #pragma unroll
                for (int b = 0; b < NB; b++) acc[b] = binit;
            }
            #pragma unroll 4
            for (int g = 0; g < 16; g++) {
                const ulonglong2 w2 = wrow[g];
                #pragma unroll
                for (int b = 0; b < NB; b++) {
                    const ulonglong2 h2 = *(const ulonglong2*)&sm[OFF_HP + b * 64 + g * 4];
                    fma2(acc[b], w2.x, h2.x);
                    fma2(acc[b], w2.y, h2.y);
                }
            }
            float* xw = &sm[OFF_XW + (t & 3) * 1024];
            #pragma unroll
            for (int b = 0; b < NB; b++) {
                float lo, hi;
                unpack2(acc[b], lo, hi);
                xw[b * 128 + k] = lo + hi;
            }
        } else if (tid >= 248 && t + 1 < Ll) {
            s_tok[((t + 1) & 1) * 8 + (tid - 248)] = seq[(b0 + tid - 248) * Ll + (t + 1)];
        }
        __syncthreads();   // s2

        // ===== D: register LSTM trigger (warps 0-7; bf16 weights, HW tanh) =====
        if (t >= 3) {
            const int w = tid >> 5, u = tid & 31;
            float hh = 0.f, cc = 0.f;
            #pragma unroll
            for (int s = 0; s < 4; s++) {
                const int slot = (t + 1 + s) & 3;
                const float* xw = &sm[OFF_XW + slot * 1024 + w * 128];
                float gI = xw[u], gF = xw[32 + u], gG = xw[64 + u], gO = xw[96 + u];
                if (s > 0) {
                    #pragma unroll
                    for (int j = 0; j < 32; j++) {
                        const float hj = __shfl_sync(0xffffffffu, hh, j);
                        const uint2 wp = *(const uint2*)&smB[(j * 32 + u) * 2];
                        gI = fmaf(__uint_as_float(wp.x << 16),         hj, gI);
                        gF = fmaf(__uint_as_float(wp.x & 0xffff0000u), hj, gF);
                        gG = fmaf(__uint_as_float(wp.y << 16),         hj, gG);
                        gO = fmaf(__uint_as_float(wp.y & 0xffff0000u), hj, gO);
                    }
                }
                float c = siga(gI) * tanha(gG);
                if (s > 0) c = fmaf(siga(gF), cc, c);
                cc = c;
                hh = siga(gO) * tanha(c);
            }
            float v = hh * sm[OFF_TW + u];
            #pragma unroll
            for (int o = 16; o > 0; o >>= 1) v += __shfl_xor_sync(0xffffffffu, v, o);
            if (u == 0) sm[OFF_PROB + w] = siga(v + sm[OFF_SC]);
        }
        __syncthreads();   // s3

        // ===== E: gh_{t+1} (threads 0-191, f32x2 j-paired) || post+poll (192-255) =====
        if (tid < 192) {
            const int k = tid;
            const ulonglong2* wrow = (const ulonglong2*)&sm[OFF_GWHH + k * 68];
            unsigned long long acc[NB];
            {
                const unsigned long long binit = pack2(sm[OFF_GBHH + k], 0.f);
                #pragma unroll
                for (int b = 0; b < NB; b++) acc[b] = binit;
            }
            #pragma unroll 4
            for (int g = 0; g < 16; g++) {
                const ulonglong2 w2 = wrow[g];
                #pragma unroll
                for (int b = 0; b < NB; b++) {
                    const ulonglong2 h2 = *(const ulonglong2*)&sm[OFF_HP + b * 64 + g * 4];
                    fma2(acc[b], w2.x, h2.x);
                    fma2(acc[b], w2.y, h2.y);
                }
            }
            #pragma unroll
            for (int b = 0; b < NB; b++) {
                float lo, hi;
                unpack2(acc[b], lo, hi);
                sm[OFF_GH + b * 192 + k] = lo + hi;
            }
        } else if (t >= 3) {
            const int i = tid - 192;                      // 64 pollers, 2 slots each
            if (i == 0) {                                 // poster
                float pv = sm[OFF_PROB + 0] + sm[OFF_PROB + 1] + sm[OFF_PROB + 2] + sm[OFF_PROB + 3]
                         + sm[OFF_PROB + 4] + sm[OFF_PROB + 5] + sm[OFF_PROB + 6] + sm[OFF_PROB + 7];
                asm volatile("st.global.cg.f32 [%0], %1;"
                             :: "l"(&d_gpart[t * NBLK + blockIdx.x]), "f"(pv + 1.f)
                             : "memory");
            }
            const float* g0 = &d_gpart[t * NBLK + i];
            const float* g1 = &d_gpart[t * NBLK + 64 + i];
            float v0, v1;
            do {
                asm volatile("ld.global.cg.f32 %0, [%1];" : "=f"(v0) : "l"(g0) : "memory");
            } while (v0 == 0.f);
            do {
                asm volatile("ld.global.cg.f32 %0, [%1];" : "=f"(v1) : "l"(g1) : "memory");
            } while (v1 == 0.f);
            sm[OFF_RED + i]      = v0 - 1.f;
            sm[OFF_RED + 64 + i] = v1 - 1.f;
        }
        __syncthreads();   // s4

        if (t >= 3) {
            // every warp reduces redundantly -> uniform do_read in registers
            const int ln = tid & 31;
            float s = sm[OFF_RED + ln] + sm[OFF_RED + 32 + ln]
                    + sm[OFF_RED + 64 + ln] + sm[OFF_RED + 96 + ln];
            #pragma unroll
            for (int o = 16; o > 0; o >>= 1) s += __shfl_xor_sync(0xffffffffu, s, o);
            const int do_read = (s > 512.f);

            if (do_read) {
                // ---- attention: q2 = A2 h + a0 ----
                if (tid < 64) {
                    const int k = tid;
                    float acc[NB];
                    #pragma unroll
                    for (int b = 0; b < NB; b++) acc[b] = sm[OFF_A0 + k];
                    #pragma unroll 4
                    for (int j = 0; j < 64; j += 4) {
                        const float w0 = sm[OFF_A2 + (j + 0) * 64 + k];
                        const float w1 = sm[OFF_A2 + (j + 1) * 64 + k];
                        const float w2 = sm[OFF_A2 + (j + 2) * 64 + k];
                        const float w3 = sm[OFF_A2 + (j + 3) * 64 + k];
                        #pragma unroll
                        for (int b = 0; b < NB; b++) {
                            const float4 h4 = *(const float4*)&sm[OFF_HP + b * 64 + j];
                            acc[b] = fmaf(w0, h4.x, acc[b]);
                            acc[b] = fmaf(w1, h4.y, acc[b]);
                            acc[b] = fmaf(w2, h4.z, acc[b]);
                            acc[b] = fmaf(w3, h4.w, acc[b]);
                        }
                    }
                    #pragma unroll
                    for (int b = 0; b < NB; b++) sm[OFF_Q2 + b * 64 + k] = acc[b];
                }
                __syncthreads();
                {   // streaming online softmax over memory (warp per batch)
                    const int w2 = tid >> 5, l2 = tid & 31;
                    const float* mb = memory + (size_t)(b0 + w2) * (Mm * Hh);
                    const float q0 = sm[OFF_Q2 + w2 * 64 + 2 * l2];
                    const float q1 = sm[OFF_Q2 + w2 * 64 + 2 * l2 + 1];
                    float mx = -3.0e38f, dn = 0.f, ra = 0.f, rb = 0.f;
                    #pragma unroll 4
                    for (int m = 0; m < Mm; m++) {
                        const float2 mmv = *(const float2*)(mb + m * 64 + 2 * l2);
                        float p = q0 * mmv.x + q1 * mmv.y;
                        #pragma unroll
                        for (int o = 16; o > 0; o >>= 1) p += __shfl_xor_sync(0xffffffffu, p, o);
                        const float nm = fmaxf(mx, p);
                        const float f  = __expf(mx - nm);
                        const float e  = __expf(p - nm);
                        dn = fmaf(dn, f, e);
                        ra = fmaf(ra, f, e * mmv.x);
                        rb = fmaf(rb, f, e * mmv.y);
                        mx = nm;
                    }
                    const float inv = 1.f / dn;
                    sm[OFF_WS + w2 * 64 + 2 * l2]     = ra * inv;
                    sm[OFF_WS + w2 * 64 + 2 * l2 + 1] = rb * inv;
                }
                __syncthreads();
                if (tid < 64) {   // retrieved = v_w ws + v_b
                    const int k = tid;
                    float acc[NB];
                    #pragma unroll
                    for (int b = 0; b < NB; b++) acc[b] = sm[OFF_VB + k];
                    #pragma unroll 4
                    for (int j = 0; j < 64; j += 4) {
                        const float w0 = sm[OFF_VW + (j + 0) * 64 + k];
                        const float w1 = sm[OFF_VW + (j + 1) * 64 + k];
                        const float w2 = sm[OFF_VW + (j + 2) * 64 + k];
                        const float w3 = sm[OFF_VW + (j + 3) * 64 + k];
                        #pragma unroll
                        for (int b = 0; b < NB; b++) {
                            const float4 s4 = *(const float4*)&sm[OFF_WS + b * 64 + j];
                            acc[b] = fmaf(w0, s4.x, acc[b]);
                            acc[b] = fmaf(w1, s4.y, acc[b]);
                            acc[b] = fmaf(w2, s4.z, acc[b]);
                            acc[b] = fmaf(w3, s4.w, acc[b]);
                        }
                    }
                    #pragma unroll
                    for (int b = 0; b < NB; b++) sm[OFF_RET + b * 64 + k] = acc[b];
                }
                __syncthreads();
                // GI = Wr . retrieved  (Wr read from global — rare path)
                if (tid < 192) {
                    const int k = tid;
                    float acc[NB];
                    #pragma unroll
                    for (int b = 0; b < NB; b++) acc[b] = 0.f;
                    const float* wr = &gwih[k * 128 + 64];
                    #pragma unroll 4
                    for (int j = 0; j < 64; j += 4) {
                        const float4 w4 = __ldg((const float4*)(wr + j));
                        #pragma unroll
                        for (int b = 0; b < NB; b++) {
                            const float4 r4 = *(const float4*)&sm[OFF_RET + b * 64 + j];
                            acc[b] = fmaf(w4.x, r4.x, acc[b]);
                            acc[b] = fmaf(w4.y, r4.y, acc[b]);
                            acc[b] = fmaf(w4.z, r4.z, acc[b]);
                            acc[b] = fmaf(w4.w, r4.w, acc[b]);
                        }
                    }
                    #pragma unroll
                    for (int b = 0; b < NB; b++) sm[OFF_GI + b * 192 + k] = acc[b];
                }
                __syncthreads();   // protect GI before next-step B
                nreads++;
            }
            read_prev = do_read;
        } else {
            read_prev = 0;
        }
        // next-step B (writes HP) is safe: gh readers of HP finished before s4
    }

    __syncthreads();
    // ---------- epilogue: logits = h @ head_w^T + head_b ----------
    if (tid < 64) {
        const int k = tid;
        float acc[NB];
        const float hb = __ldg(&headb[k]);
        #pragma unroll
        for (int b = 0; b < NB; b++) acc[b] = hb;
        #pragma unroll 4
        for (int j = 0; j < 64; j += 4) {
            const float4 w4 = __ldg((const float4*)(headw + k * 64 + j));
            #pragma unroll
            for (int b = 0; b < NB; b++) {
                const float4 h4 = *(const float4*)&sm[OFF_HP + b * 64 + j];
                acc[b] = fmaf(w4.x, h4.x, acc[b]);
                acc[b] = fmaf(w4.y, h4.y, acc[b]);
                acc[b] = fmaf(w4.z, h4.z, acc[b]);
                acc[b] = fmaf(w4.w, h4.w, acc[b]);
            }
        }
        #pragma unroll
        for (int b = 0; b < NB; b++) out[(size_t)(b0 + b) * Vv + k] = acc[b];
    }
    if (blockIdx.x == 0 && tid == 0) {
        const float rr = (float)nreads * (1.f / (float)Ll);
        for (int i = Bb * Vv; i < out_size; i++) out[i] = rr;
    }
}

extern "C" void kernel_launch(void* const* d_in, const int* in_sizes, int n_in,
                              void* d_out, int out_size) {
    const int*   seq    = (const int*)  d_in[0];
    const float* memory = (const float*)d_in[1];
    const float* embed  = (const float*)d_in[2];
    const float* gwih   = (const float*)d_in[3];
    const float* gwhh   = (const float*)d_in[4];
    const float* gbih   = (const float*)d_in[5];
    const float* gbhh   = (const float*)d_in[6];
    const float* qw     = (const float*)d_in[7];
    const float* qb     = (const float*)d_in[8];
    const float* kw     = (const float*)d_in[9];
    /* k_b (d_in[10]) cancels in softmax — unused */
    const float* vw     = (const float*)d_in[11];
    const float* vb     = (const float*)d_in[12];
    const float* lwih   = (const float*)d_in[13];
    const float* lwhh   = (const float*)d_in[14];
    const float* lbih   = (const float*)d_in[15];
    const float* lbhh   = (const float*)d_in[16];
    const float* trigw  = (const float*)d_in[17];
    const float* trigb  = (const float*)d_in[18];
    const float* headw  = (const float*)d_in[19];
    const float* headb  = (const float*)d_in[20];
    float* out = (float*)d_out;

    cudaFuncSetAttribute(model_kernel,
                         cudaFuncAttributeMaxDynamicSharedMemorySize, SMEM_BYTES);

    prep_kernel<<<64, 256>>>(embed, gwih, gbih, kw, qw, qb);
    model_kernel<<<NBLK, NT, SMEM_BYTES>>>(seq, memory, gwih, gwhh, gbhh,
                                           vw, vb, lwih, lwhh, lbih, lbhh,
                                           trigw, trigb, headw, headb,
                                           out, out_size);
}

// round 17
// speedup vs baseline: 2.0206x; 1.0247x over previous
#include <cuda_runtime.h>
#include <math.h>

#define Bb   1024
#define Ll   256
#define Mm   256
#define Hh   64
#define Vv   64
#define NB   8      // batches per block
#define NBLK 128
#define NT   256

// ---------------- device scratch ----------------
__device__ float d_E2[Vv * 192];       // embed @ Wx^T + b_ih   (64 x 192)
__device__ float d_A2[Hh * Hh];        // (q_w^T k_w) / 8  stored [a][l]
__device__ float d_a0[Hh];             // (q_b^T k_w) / 8
__device__ float d_gpart[Ll * NBLK];   // per-step per-block partial sums (+1.0 sentinel)

__device__ __forceinline__ float sigf(float x)     { return 1.f / (1.f + __expf(-x)); }
__device__ __forceinline__ float tanhfast(float x) { return 2.f / (1.f + __expf(-2.f * x)) - 1.f; }

// HW tanh (MUFU.TANH) — trigger path only
__device__ __forceinline__ float tanha(float x) {
    float r;
    asm("tanh.approx.f32 %0, %1;" : "=f"(r) : "f"(x));
    return r;
}
__device__ __forceinline__ float siga(float x) {
    return fmaf(tanha(0.5f * x), 0.5f, 0.5f);
}

__device__ __forceinline__ unsigned long long pack2(float a, float b) {
    unsigned long long r;
    asm("mov.b64 %0, {%1, %2};" : "=l"(r) : "f"(a), "f"(b));
    return r;
}
__device__ __forceinline__ void unpack2(unsigned long long v, float& a, float& b) {
    asm("mov.b64 {%0, %1}, %2;" : "=f"(a), "=f"(b) : "l"(v));
}
__device__ __forceinline__ void fma2(unsigned long long& d, unsigned long long a, unsigned long long b) {
    asm("fma.rn.f32x2 %0, %1, %2, %0;" : "+l"(d) : "l"(a), "l"(b));
}

// bf16x2 helpers (trigger path)
__device__ __forceinline__ unsigned int cvt_bf2(float hi, float lo) {
    unsigned int r;
    asm("cvt.rn.bf16x2.f32 %0, %1, %2;" : "=r"(r) : "f"(hi), "f"(lo));
    return r;
}
__device__ __forceinline__ void hfma2b(unsigned int& d, unsigned int a, unsigned int b) {
    asm("fma.rn.bf16x2 %0, %1, %2, %0;" : "+r"(d) : "r"(a), "r"(b));
}

// round-to-nearest-even bf16, returned as f32 bit-pattern (high 16 bits kept)
__device__ __forceinline__ unsigned int bfr(float x) {
    unsigned int b = __float_as_uint(x);
    return (b + 0x7fffu + ((b >> 16) & 1u)) & 0xffff0000u;
}

// ---------------- prep ----------------
__global__ void prep_kernel(const float* __restrict__ embed,
                            const float* __restrict__ gwih,
                            const float* __restrict__ gbih,
                            const float* __restrict__ kw,
                            const float* __restrict__ qw,
                            const float* __restrict__ qb) {
    const int idx = blockIdx.x * blockDim.x + threadIdx.x;
    const int stride = gridDim.x * blockDim.x;
    for (int i = idx; i < Vv * 192; i += stride) {
        const int v = i / 192, k = i % 192;
        float s = gbih[k];
        const float* e = embed + v * Hh;
        const float* w = gwih + k * (2 * Hh);
        #pragma unroll 8
        for (int j = 0; j < Hh; j++) s = fmaf(e[j], w[j], s);
        d_E2[i] = s;
    }
    for (int i = idx; i < Hh * Hh; i += stride) {
        const int a = i >> 6, l = i & 63;
        float s = 0.f;
        for (int t = 0; t < Hh; t++) s = fmaf(kw[t * Hh + a], qw[t * Hh + l], s);
        d_A2[i] = s * 0.125f;
    }
    for (int i = idx; i < Hh; i += stride) {
        float s = 0.f;
        for (int t = 0; t < Hh; t++) s = fmaf(kw[t * Hh + i], qb[t], s);
        d_a0[i] = s * 0.125f;
    }
    for (int i = idx; i < Ll * NBLK; i += stride) d_gpart[i] = 0.f;
}

// ---------------- SMEM layout (float offsets) ----------------
#define OFF_GWHH  0       /* gwhh [k<192][j<64] pad 68 = 13056 (row-major, j-contig) */
#define OFF_E2    13056   /* full E2 table [v<64][k<192] = 12288 */
#define OFF_LWIH  25344   /* lwih [k<128][j<64] pad 68 = 8704 (row-major, j-contig) */
#define OFF_LWHHB 34048   /* lwhh bf16x2 [j<32][u<32][2] = 2048 uint32 (8KB) */
#define OFF_A2    36096   /* A2^T [l][a] = 4096 */
#define OFF_VW    40192   /* vw^T [j][k] = 4096 */
#define OFF_GBHH  44288   /* 192 */
#define OFF_LB2   44480   /* 128 lbih+lbhh */
#define OFF_A0    44608   /* 64 */
#define OFF_VB    44672   /* 64 */
#define OFF_TW    44736   /* 32 */
#define OFF_SC    44768   /* 4 */
#define OFF_HP    44772   /* 8x64 h state (16B-aligned) */
#define OFF_XW    45284   /* ring 4 x 8 x 128 (bias folded) */
#define OFF_GH    49380   /* 8 x 192 */
#define OFF_GI    50916   /* 8 x 192 */
#define OFF_Q2    52452   /* 8x64 */
#define OFF_WS    52964   /* 8x64 */
#define OFF_RET   53476   /* 8x64 */
#define OFF_PROB  53988   /* 8 */
#define OFF_RED   53996   /* 128 */
#define OFF_TOK   54124   /* 2 x 8 ints */
#define SMEM_FLOATS 54140
#define SMEM_BYTES  (SMEM_FLOATS * 4)

__global__ void __launch_bounds__(NT, 1) model_kernel(
    const int*   __restrict__ seq,
    const float* __restrict__ memory,
    const float* __restrict__ gwih,
    const float* __restrict__ gwhh,
    const float* __restrict__ gbhh,
    const float* __restrict__ vw,
    const float* __restrict__ vb,
    const float* __restrict__ lwih,
    const float* __restrict__ lwhh,
    const float* __restrict__ lbih,
    const float* __restrict__ lbhh,
    const float* __restrict__ trigw,
    const float* __restrict__ trigb,
    const float* __restrict__ headw,
    const float* __restrict__ headb,
    float* __restrict__ out,
    int out_size)
{
    extern __shared__ float sm[];
    const int tid = threadIdx.x;
    const int b0  = blockIdx.x * NB;
    int* s_tok = (int*)(sm + OFF_TOK);
    unsigned int* smB = (unsigned int*)(sm + OFF_LWHHB);

    // ---- weight staging ----
    for (int i = tid; i < 192 * 64; i += NT) {           // gwhh row-major, pad 68
        const int k = i >> 6, j = i & 63;
        sm[OFF_GWHH + k * 68 + j] = gwhh[i];
    }
    for (int i = tid; i < 12288; i += NT)                // full E2 table
        sm[OFF_E2 + i] = d_E2[i];
    for (int i = tid; i < 128 * 64; i += NT) {           // lwih row-major, pad 68
        const int k = i >> 6, j = i & 63;
        sm[OFF_LWIH + k * 68 + j] = lwih[i];
    }
    for (int i = tid; i < 2048; i += NT) {               // lwhh -> bf16 pairs [j][u][p]
        const int j = i >> 6, u = (i >> 1) & 31, p = i & 1;
        const float w0 = lwhh[((2 * p + 0) * 32 + u) * 32 + j];
        const float w1 = lwhh[((2 * p + 1) * 32 + u) * 32 + j];
        smB[i] = (bfr(w0) >> 16) | bfr(w1);
    }
    for (int i = tid; i < 4096; i += NT)                 // A2^T [l][a]
        sm[OFF_A2 + i] = d_A2[(i % 64) * 64 + (i / 64)];
    for (int i = tid; i < 4096; i += NT)                 // vw^T [j][k]
        sm[OFF_VW + i] = vw[(i % 64) * 64 + (i / 64)];
    for (int i = tid; i < 192; i += NT) sm[OFF_GBHH + i] = gbhh[i];
    for (int i = tid; i < 128; i += NT) sm[OFF_LB2 + i] = lbih[i] + lbhh[i];
    for (int i = tid; i < 64; i += NT)  { sm[OFF_A0 + i] = d_a0[i]; sm[OFF_VB + i] = vb[i]; }
    for (int i = tid; i < 32; i += NT)  sm[OFF_TW + i] = trigw[i];
    if (tid == 0) sm[OFF_SC] = trigb[0];
    for (int i = tid; i < NB * Hh; i += NT) sm[OFF_HP + i] = 0.f;
    for (int i = tid; i < 1536; i += NT) sm[OFF_GH + i] = gbhh[i % 192];   // gh for t=0 (h=0)
    if (tid < NB) s_tok[tid] = seq[(b0 + tid) * Ll + 0];                    // tokens t=0 -> slot 0
    __syncthreads();

    int read_prev = 0;
    int nreads = 0;

    for (int t = 0; t < Ll; t++) {
        // ===== B: GRU combine -> new h (exact nonlinearities) =====
        #pragma unroll
        for (int it = tid; it < NB * Hh; it += NT) {
            const int b = it >> 6, k = it & 63;
            const int tok = s_tok[(t & 1) * 8 + b];
            float gi_r = sm[OFF_E2 + tok * 192 + k];
            float gi_z = sm[OFF_E2 + tok * 192 + 64 + k];
            float gi_n = sm[OFF_E2 + tok * 192 + 128 + k];
            if (read_prev) {
                gi_r += sm[OFF_GI + b * 192 + k];
                gi_z += sm[OFF_GI + b * 192 + 64 + k];
                gi_n += sm[OFF_GI + b * 192 + 128 + k];
            }
            const float gh_r = sm[OFF_GH + b * 192 + k];
            const float gh_z = sm[OFF_GH + b * 192 + 64 + k];
            const float gh_n = sm[OFF_GH + b * 192 + 128 + k];
            const float r = sigf(gi_r + gh_r);
            const float z = sigf(gi_z + gh_z);
            const float n = tanhfast(fmaf(r, gh_n, gi_n));
            const float h = sm[OFF_HP + b * 64 + k];
            sm[OFF_HP + b * 64 + k] = n + z * (h - n);   // (1-z)n + z h
        }
        __syncthreads();   // s1

        // ===== C: xW_t -> ring slot (ALL 256 threads, batch-split 4+4) =====
        {
            const int k = tid & 127, half = tid >> 7;
            const ulonglong2* wrow = (const ulonglong2*)&sm[OFF_LWIH + k * 68];
            unsigned long long acc[4];
            {
                const unsigned long long binit = pack2(sm[OFF_LB2 + k], 0.f);
                #pragma unroll
                for (int b = 0; b < 4; b++) acc[b] = binit;
            }
            #pragma unroll 4
            for (int g = 0; g < 16; g++) {
                const ulonglong2 w2 = wrow[g];
                #pragma unroll
                for (int b = 0; b < 4; b++) {
                    const ulonglong2 h2 = *(const ulonglong2*)&sm[OFF_HP + (half * 4 + b) * 64 + g * 4];
                    fma2(acc[b], w2.x, h2.x);
                    fma2(acc[b], w2.y, h2.y);
                }
            }
            float* xw = &sm[OFF_XW + (t & 3) * 1024];
            #pragma unroll
            for (int b = 0; b < 4; b++) {
                float lo, hi;
                unpack2(acc[b], lo, hi);
                xw[(half * 4 + b) * 128 + k] = lo + hi;
            }
        }
        __syncthreads();   // s2

        // ===== D: register LSTM trigger (warps 0-7; bf16x2 HFMA2 matvec, HW tanh) =====
        if (t >= 3) {
            const int w = tid >> 5, u = tid & 31;
            float hh = 0.f, cc = 0.f;
            unsigned int hh2 = 0u;                       // bf16x2 (hh, hh)
            #pragma unroll
            for (int s = 0; s < 4; s++) {
                const int slot = (t + 1 + s) & 3;
                const float* xw = &sm[OFF_XW + slot * 1024 + w * 128];
                unsigned int aIF = cvt_bf2(xw[32 + u], xw[u]);        // hi=gF, lo=gI
                unsigned int aGO = cvt_bf2(xw[96 + u], xw[64 + u]);   // hi=gO, lo=gG
                if (s > 0) {
                    #pragma unroll
                    for (int j = 0; j < 32; j++) {
                        const unsigned int hj2 = __shfl_sync(0xffffffffu, hh2, j);
                        const uint2 wp = *(const uint2*)&smB[(j * 32 + u) * 2];
                        hfma2b(aIF, wp.x, hj2);
                        hfma2b(aGO, wp.y, hj2);
                    }
                }
                const float gI = __uint_as_float(aIF << 16);
                const float gF = __uint_as_float(aIF & 0xffff0000u);
                const float gG = __uint_as_float(aGO << 16);
                const float gO = __uint_as_float(aGO & 0xffff0000u);
                float c = siga(gI) * tanha(gG);
                if (s > 0) c = fmaf(siga(gF), cc, c);
                cc = c;
                hh = siga(gO) * tanha(c);
                hh2 = cvt_bf2(hh, hh);
            }
            float v = hh * sm[OFF_TW + u];
            #pragma unroll
            for (int o = 16; o > 0; o >>= 1) v += __shfl_xor_sync(0xffffffffu, v, o);
            if (u == 0) sm[OFF_PROB + w] = siga(v + sm[OFF_SC]);
        }
        __syncthreads();   // s3

        // ===== E: gh_{t+1} (threads 0-191, f32x2) || tokens + post + poll (192-255) =====
        if (tid < 192) {
            const int k = tid;
            const ulonglong2* wrow = (const ulonglong2*)&sm[OFF_GWHH + k * 68];
            unsigned long long acc[NB];
            {
                const unsigned long long binit = pack2(sm[OFF_GBHH + k], 0.f);
                #pragma unroll
                for (int b = 0; b < NB; b++) acc[b] = binit;
            }
            #pragma unroll 4
            for (int g = 0; g < 16; g++) {
                const ulonglong2 w2 = wrow[g];
                #pragma unroll
                for (int b = 0; b < NB; b++) {
                    const ulonglong2 h2 = *(const ulonglong2*)&sm[OFF_HP + b * 64 + g * 4];
                    fma2(acc[b], w2.x, h2.x);
                    fma2(acc[b], w2.y, h2.y);
                }
            }
            #pragma unroll
            for (int b = 0; b < NB; b++) {
                float lo, hi;
                unpack2(acc[b], lo, hi);
                sm[OFF_GH + b * 192 + k] = lo + hi;
            }
        } else {
            const int i = tid - 192;                      // 64 threads
            if (i < 8 && t + 1 < Ll)
                s_tok[((t + 1) & 1) * 8 + i] = seq[(b0 + i) * Ll + (t + 1)];
            if (t >= 3) {
                if (i == 0) {                             // poster
                    float pv = sm[OFF_PROB + 0] + sm[OFF_PROB + 1] + sm[OFF_PROB + 2] + sm[OFF_PROB + 3]
                             + sm[OFF_PROB + 4] + sm[OFF_PROB + 5] + sm[OFF_PROB + 6] + sm[OFF_PROB + 7];
                    asm volatile("st.global.cg.f32 [%0], %1;"
                                 :: "l"(&d_gpart[t * NBLK + blockIdx.x]), "f"(pv + 1.f)
                                 : "memory");
                }
                const float* g0 = &d_gpart[t * NBLK + i];
                const float* g1 = &d_gpart[t * NBLK + 64 + i];
                float v0, v1;
                do {
                    asm volatile("ld.global.cg.f32 %0, [%1];" : "=f"(v0) : "l"(g0) : "memory");
                } while (v0 == 0.f);
                do {
                    asm volatile("ld.global.cg.f32 %0, [%1];" : "=f"(v1) : "l"(g1) : "memory");
                } while (v1 == 0.f);
                sm[OFF_RED + i]      = v0 - 1.f;
                sm[OFF_RED + 64 + i] = v1 - 1.f;
            }
        }
        __syncthreads();   // s4

        if (t >= 3) {
            // every warp reduces redundantly -> uniform do_read in registers
            const int ln = tid & 31;
            float s = sm[OFF_RED + ln] + sm[OFF_RED + 32 + ln]
                    + sm[OFF_RED + 64 + ln] + sm[OFF_RED + 96 + ln];
            #pragma unroll
            for (int o = 16; o > 0; o >>= 1) s += __shfl_xor_sync(0xffffffffu, s, o);
            const int do_read = (s > 512.f);

            if (do_read) {
                // ---- attention: q2 = A2 h + a0 ----
                if (tid < 64) {
                    const int k = tid;
                    float acc[NB];
                    #pragma unroll
                    for (int b = 0; b < NB; b++) acc[b] = sm[OFF_A0 + k];
                    #pragma unroll 4
                    for (int j = 0; j < 64; j += 4) {
                        const float w0 = sm[OFF_A2 + (j + 0) * 64 + k];
                        const float w1 = sm[OFF_A2 + (j + 1) * 64 + k];
                        const float w2 = sm[OFF_A2 + (j + 2) * 64 + k];
                        const float w3 = sm[OFF_A2 + (j + 3) * 64 + k];
                        #pragma unroll
                        for (int b = 0; b < NB; b++) {
                            const float4 h4 = *(const float4*)&sm[OFF_HP + b * 64 + j];
                            acc[b] = fmaf(w0, h4.x, acc[b]);
                            acc[b] = fmaf(w1, h4.y, acc[b]);
                            acc[b] = fmaf(w2, h4.z, acc[b]);
                            acc[b] = fmaf(w3, h4.w, acc[b]);
                        }
                    }
                    #pragma unroll
                    for (int b = 0; b < NB; b++) sm[OFF_Q2 + b * 64 + k] = acc[b];
                }
                __syncthreads();
                {   // streaming online softmax over memory (warp per batch)
                    const int w2 = tid >> 5, l2 = tid & 31;
                    const float* mb = memory + (size_t)(b0 + w2) * (Mm * Hh);
                    const float q0 = sm[OFF_Q2 + w2 * 64 + 2 * l2];
                    const float q1 = sm[OFF_Q2 + w2 * 64 + 2 * l2 + 1];
                    float mx = -3.0e38f, dn = 0.f, ra = 0.f, rb = 0.f;
                    #pragma unroll 4
                    for (int m = 0; m < Mm; m++) {
                        const float2 mmv = *(const float2*)(mb + m * 64 + 2 * l2);
                        float p = q0 * mmv.x + q1 * mmv.y;
                        #pragma unroll
                        for (int o = 16; o > 0; o >>= 1) p += __shfl_xor_sync(0xffffffffu, p, o);
                        const float nm = fmaxf(mx, p);
                        const float f  = __expf(mx - nm);
                        const float e  = __expf(p - nm);
                        dn = fmaf(dn, f, e);
                        ra = fmaf(ra, f, e * mmv.x);
                        rb = fmaf(rb, f, e * mmv.y);
                        mx = nm;
                    }
                    const float inv = 1.f / dn;
                    sm[OFF_WS + w2 * 64 + 2 * l2]     = ra * inv;
                    sm[OFF_WS + w2 * 64 + 2 * l2 + 1] = rb * inv;
                }
                __syncthreads();
                if (tid < 64) {   // retrieved = v_w ws + v_b
                    const int k = tid;
                    float acc[NB];
                    #pragma unroll
                    for (int b = 0; b < NB; b++) acc[b] = sm[OFF_VB + k];
                    #pragma unroll 4
                    for (int j = 0; j < 64; j += 4) {
                        const float w0 = sm[OFF_VW + (j + 0) * 64 + k];
                        const float w1 = sm[OFF_VW + (j + 1) * 64 + k];
                        const float w2 = sm[OFF_VW + (j + 2) * 64 + k];
                        const float w3 = sm[OFF_VW + (j + 3) * 64 + k];
                        #pragma unroll
                        for (int b = 0; b < NB; b++) {
                            const float4 s4 = *(const float4*)&sm[OFF_WS + b * 64 + j];
                            acc[b] = fmaf(w0, s4.x, acc[b]);
                            acc[b] = fmaf(w1, s4.y, acc[b]);
                            acc[b] = fmaf(w2, s4.z, acc[b]);
                            acc[b] = fmaf(w3, s4.w, acc[b]);
                        }
                    }
                    #pragma unroll
                    for (int b = 0; b < NB; b++) sm[OFF_RET + b * 64 + k] = acc[b];
                }
                __syncthreads();
                // GI = Wr . retrieved  (Wr read from global — rare path)
                if (tid < 192) {
                    const int k = tid;
                    float acc[NB];
                    #pragma unroll
                    for (int b = 0; b < NB; b++) acc[b] = 0.f;
                    const float* wr = &gwih[k * 128 + 64];
                    #pragma unroll 4
                    for (int j = 0; j < 64; j += 4) {
                        const float4 w4 = __ldg((const float4*)(wr + j));
                        #pragma unroll
                        for (int b = 0; b < NB; b++) {
                            const float4 r4 = *(const float4*)&sm[OFF_RET + b * 64 + j];
                            acc[b] = fmaf(w4.x, r4.x, acc[b]);
                            acc[b] = fmaf(w4.y, r4.y, acc[b]);
                            acc[b] = fmaf(w4.z, r4.z, acc[b]);
                            acc[b] = fmaf(w4.w, r4.w, acc[b]);
                        }
                    }
                    #pragma unroll
                    for (int b = 0; b < NB; b++) sm[OFF_GI + b * 192 + k] = acc[b];
                }
                __syncthreads();   // protect GI before next-step B
                nreads++;
            }
            read_prev = do_read;
        } else {
            read_prev = 0;
        }
        // next-step B (writes HP) is safe: gh readers of HP finished before s4
    }

    __syncthreads();
    // ---------- epilogue: logits = h @ head_w^T + head_b ----------
    if (tid < 64) {
        const int k = tid;
        float acc[NB];
        const float hb = __ldg(&headb[k]);
        #pragma unroll
        for (int b = 0; b < NB; b++) acc[b] = hb;
        #pragma unroll 4
        for (int j = 0; j < 64; j += 4) {
            const float4 w4 = __ldg((const float4*)(headw + k * 64 + j));
            #pragma unroll
            for (int b = 0; b < NB; b++) {
                const float4 h4 = *(const float4*)&sm[OFF_HP + b * 64 + j];
                acc[b] = fmaf(w4.x, h4.x, acc[b]);
                acc[b] = fmaf(w4.y, h4.y, acc[b]);
                acc[b] = fmaf(w4.z, h4.z, acc[b]);
                acc[b] = fmaf(w4.w, h4.w, acc[b]);
            }
        }
        #pragma unroll
        for (int b = 0; b < NB; b++) out[(size_t)(b0 + b) * Vv + k] = acc[b];
    }
    if (blockIdx.x == 0 && tid == 0) {
        const float rr = (float)nreads * (1.f / (float)Ll);
        for (int i = Bb * Vv; i < out_size; i++) out[i] = rr;
    }
}

extern "C" void kernel_launch(void* const* d_in, const int* in_sizes, int n_in,
                              void* d_out, int out_size) {
    const int*   seq    = (const int*)  d_in[0];
    const float* memory = (const float*)d_in[1];
    const float* embed  = (const float*)d_in[2];
    const float* gwih   = (const float*)d_in[3];
    const float* gwhh   = (const float*)d_in[4];
    const float* gbih   = (const float*)d_in[5];
    const float* gbhh   = (const float*)d_in[6];
    const float* qw     = (const float*)d_in[7];
    const float* qb     = (const float*)d_in[8];
    const float* kw     = (const float*)d_in[9];
    /* k_b (d_in[10]) cancels in softmax — unused */
    const float* vw     = (const float*)d_in[11];
    const float* vb     = (const float*)d_in[12];
    const float* lwih   = (const float*)d_in[13];
    const float* lwhh   = (const float*)d_in[14];
    const float* lbih   = (const float*)d_in[15];
    const float* lbhh   = (const float*)d_in[16];
    const float* trigw  = (const float*)d_in[17];
    const float* trigb  = (const float*)d_in[18];
    const float* headw  = (const float*)d_in[19];
    const float* headb  = (const float*)d_in[20];
    float* out = (float*)d_out;

    cudaFuncSetAttribute(model_kernel,
                         cudaFuncAttributeMaxDynamicSharedMemorySize, SMEM_BYTES);

    prep_kernel<<<64, 256>>>(embed, gwih, gbih, kw, qw, qb);
    model_kernel<<<NBLK, NT, SMEM_BYTES>>>(seq, memory, gwih, gwhh, gbhh,
                                           vw, vb, lwih, lwhh, lbih, lbhh,
                                           trigw, trigb, headw, headb,
                                           out, out_size);
}